// round 8
// baseline (speedup 1.0000x reference)
#include <cuda_runtime.h>
#include <math.h>

#define B   256
#define NF  10000
#define H   768
#define K   512
#define NT  8
#define QN  (2*NT-1)
#define TOK (B*K)

// ---------------- scratch ----------------
__device__ __align__(16) float g_G[NT*H];
__device__ float g_SG[NT];
__device__ float g_Q[QN];
__device__ float g_Se[NF+1];
__device__ float g_Se2[NF+1];
__device__ __align__(16) float g_D[(NF+1)*NT];
__device__ float4 g_tok[TOK];

// ---------------- kernel 0: zero g_G for gvec atomics ---------------------------
__global__ void zero_G_kernel() {
    int i = blockIdx.x * 1024 + threadIdx.x;
    if (i < NT*H) g_G[i] = 0.0f;
}

// ---------------- kernel 1: G_k = w2^T c_k (+ b2 into k=0) ----------------------
#define GV_HB 32
#define GV_HC (H / GV_HB)
__global__ void gvec_kernel(const float* __restrict__ w1, const float* __restrict__ b1,
                            const float* __restrict__ w2, const float* __restrict__ b2) {
    __shared__ float sc[NT * GV_HC];
    int tid = threadIdx.x;                  // 128
    int d   = blockIdx.x * 128 + tid;
    int h0  = blockIdx.y * GV_HC;

    if (tid < GV_HC) {
        int h = h0 + tid;
        float a    = w1[h];
        float beta = b1[h];
        float phi = 0.3989422804f * expf(-0.5f * beta * beta);
        float Phi = 0.5f * (1.0f + erff(beta * 0.7071067812f));
        sc[0*GV_HC + tid] = beta * Phi;                 // gelu(beta)
        sc[1*GV_HC + tid] = (Phi + beta * phi) * a;     // gelu'(beta)*a
        float He_km2 = 1.0f, He_km1 = beta, fact = 1.0f, apow = a;
#pragma unroll
        for (int k = 2; k < NT; k++) {
            fact *= (float)k;
            apow *= a;
            float s  = (k & 1) ? -1.0f : 1.0f;
            float gk = phi * s * ((float)k * He_km2 - beta * He_km1);
            sc[k*GV_HC + tid] = gk * apow / fact;
            float He_k = beta * He_km1 - (float)(k - 1) * He_km2;
            He_km2 = He_km1; He_km1 = He_k;
        }
    }
    __syncthreads();

    float acc[NT];
#pragma unroll
    for (int k = 0; k < NT; k++) acc[k] = 0.0f;
#pragma unroll 4
    for (int h = 0; h < GV_HC; h++) {
        float w = w2[(size_t)(h0 + h) * H + d];
#pragma unroll
        for (int k = 0; k < NT; k++) acc[k] = fmaf(sc[k*GV_HC + h], w, acc[k]);
    }
    if (blockIdx.y == 0) acc[0] += b2[d];
#pragma unroll
    for (int k = 0; k < NT; k++) atomicAdd(&g_G[k*H + d], acc[k]);
}

// ---------------- kernel 1c: SG_k and Q_m (1 block, 768 threads) -----------------
__global__ void poly_stats_kernel() {
    __shared__ float s[NT + NT*(NT+1)/2];
    int d = threadIdx.x;
    int lane = d & 31;
    if (d < NT + NT*(NT+1)/2) s[d] = 0.0f;
    __syncthreads();
    float g[NT];
#pragma unroll
    for (int k = 0; k < NT; k++) g[k] = g_G[k*H + d];

#define BRED(slot, expr) { float _v = (expr); \
    _v += __shfl_down_sync(0xffffffffu, _v, 16); \
    _v += __shfl_down_sync(0xffffffffu, _v, 8);  \
    _v += __shfl_down_sync(0xffffffffu, _v, 4);  \
    _v += __shfl_down_sync(0xffffffffu, _v, 2);  \
    _v += __shfl_down_sync(0xffffffffu, _v, 1);  \
    if (lane == 0) atomicAdd(&s[slot], _v); }

#pragma unroll
    for (int k = 0; k < NT; k++) BRED(k, g[k]);
    {
        int idx = NT;
#pragma unroll
        for (int k = 0; k < NT; k++)
#pragma unroll
            for (int l = k; l < NT; l++) { BRED(idx, g[k]*g[l]); idx++; }
    }
    __syncthreads();
    if (d == 0) {
        for (int k = 0; k < NT; k++) g_SG[k] = s[k];
        float q[QN];
        for (int m = 0; m < QN; m++) q[m] = 0.0f;
        int idx = NT;
        for (int k = 0; k < NT; k++)
            for (int l = k; l < NT; l++) {
                q[k+l] += (k == l ? 1.0f : 2.0f) * s[idx];
                idx++;
            }
        for (int m = 0; m < QN; m++) g_Q[m] = q[m];
    }
}

// ---------------- kernel 1d: per-emb-row Se, Se2, D_k (warp x 2 rows) ------------
#define ES_TILES ((NF + 2) / 2)             // 5001 two-row tiles
__global__ void __launch_bounds__(256, 5) emb_stats_kernel(const float* __restrict__ emb) {
    __shared__ float4 sG[NT * 192];         // 24 KB
    int tid  = threadIdx.x;
    int lane = tid & 31, warp = tid >> 5;   // 8 warps
    const float4* G4 = (const float4*)g_G;
    for (int i = tid; i < NT * 192; i += 256) sG[i] = G4[i];
    __syncthreads();

    const float4* emb4 = (const float4*)emb;
    int gw = blockIdx.x * 8 + warp;
    int nw = gridDim.x * 8;

    for (int tile = gw; tile < ES_TILES; tile += nw) {
        int r0 = tile * 2;
        int nrow = NF + 1 - r0; if (nrow > 2) nrow = 2;

        float acc[2][NT+2];
#pragma unroll
        for (int t = 0; t < 2; t++)
#pragma unroll
            for (int i = 0; i < NT+2; i++) acc[t][i] = 0.0f;

#pragma unroll
        for (int j = 0; j < 6; j++) {
            int dg = lane + 32*j;
            float4 e[2];
#pragma unroll
            for (int t = 0; t < 2; t++)
                e[t] = (t < nrow) ? __ldg(&emb4[(size_t)(r0 + t) * 192 + dg])
                                  : make_float4(0.f, 0.f, 0.f, 0.f);
#pragma unroll
            for (int t = 0; t < 2; t++) {
                acc[t][0] += e[t].x + e[t].y + e[t].z + e[t].w;
                acc[t][1] += e[t].x*e[t].x + e[t].y*e[t].y + e[t].z*e[t].z + e[t].w*e[t].w;
            }
#pragma unroll
            for (int k = 0; k < NT; k++) {
                float4 g = sG[k*192 + dg];
#pragma unroll
                for (int t = 0; t < 2; t++)
                    acc[t][2+k] += e[t].x*g.x + e[t].y*g.y + e[t].z*g.z + e[t].w*g.w;
            }
        }
#pragma unroll
        for (int t = 0; t < 2; t++)
#pragma unroll
            for (int i = 0; i < NT+2; i++) {
                float v = acc[t][i];
                v += __shfl_down_sync(0xffffffffu, v, 16);
                v += __shfl_down_sync(0xffffffffu, v, 8);
                v += __shfl_down_sync(0xffffffffu, v, 4);
                v += __shfl_down_sync(0xffffffffu, v, 2);
                v += __shfl_down_sync(0xffffffffu, v, 1);
                acc[t][i] = v;
            }
        if (lane == 0) {
            for (int t = 0; t < nrow; t++) {
                int r = r0 + t;
                g_Se[r]  = acc[t][0];
                g_Se2[r] = acc[t][1];
                float4* D4 = (float4*)&g_D[r * NT];
                D4[0] = make_float4(acc[t][2], acc[t][3], acc[t][4], acc[t][5]);
                D4[1] = make_float4(acc[t][6], acc[t][7], acc[t][8], acc[t][9]);
            }
        }
    }
}

// ---------------- kernel 2: top-512 + fused closed-form LN stats -----------------
// key = (abs_bits<<32) | ~idx. Bits 63, 31..14 constant across real keys.
// Binary search done 2 bits per round: 3 thresholds counted at once, two counts
// packed into one 32-bit redux word (per-field sums <= 10240 < 2^16, no carry).
#define TK_T 512
#define TK_R 20      // 512*20 = 10240 >= NF
__global__ void __launch_bounds__(TK_T, 2) topk_kernel(const float* __restrict__ x,
                                                       float* __restrict__ out,
                                                       int write_mask) {
    __shared__ float xrow[NF];
    __shared__ unsigned long long cand[K];
    __shared__ int wsum[16];
    __shared__ int wsum2[16];
    __shared__ int s_ge, s_ge2;
    __shared__ int scnt;

    int b    = blockIdx.x;
    int tid  = threadIdx.x;
    int lane = tid & 31, warp = tid >> 5;
    const float4* xr4 = (const float4*)(x + (size_t)b * NF);
    for (int i = tid; i < NF/4; i += TK_T) ((float4*)xrow)[i] = xr4[i];
    if (tid == 0) scnt = 0;
    __syncthreads();

    unsigned long long keys[TK_R];
#pragma unroll
    for (int r = 0; r < TK_R; r++) {
        int i = tid + r * TK_T;
        unsigned long long kb = 0ull;
        if (i < NF) {
            unsigned int ab = __float_as_uint(fabsf(xrow[i]));
            kb = ((unsigned long long)ab << 32) | (unsigned int)(~i);
        }
        keys[r] = kb;
    }

#define COUNT_GE(trial, res) { \
    int _c = 0; \
    _Pragma("unroll") \
    for (int _r = 0; _r < TK_R; _r++) _c += (keys[_r] >= (trial)) ? 1 : 0; \
    _c = __reduce_add_sync(0xffffffffu, _c); \
    if (lane == 0) wsum[warp] = _c; \
    __syncthreads(); \
    if (warp == 0) { \
        int _t = (lane < 16) ? wsum[lane] : 0; \
        _t = __reduce_add_sync(0xffffffffu, _t); \
        if (lane == 0) s_ge = _t; \
    } \
    __syncthreads(); \
    res = s_ge; }

// count at 3 thresholds q3>q2>q1 simultaneously; c3,c2 packed (c3<<16)|c2.
#define COUNT3(q3v, q2v, q1v, c3r, c2r, c1r) { \
    int _a3 = 0, _a2 = 0, _a1 = 0; \
    _Pragma("unroll") \
    for (int _r = 0; _r < TK_R; _r++) { \
        _a3 += (keys[_r] >= (q3v)) ? 1 : 0; \
        _a2 += (keys[_r] >= (q2v)) ? 1 : 0; \
        _a1 += (keys[_r] >= (q1v)) ? 1 : 0; \
    } \
    int _p = (_a3 << 16) | _a2; \
    _p  = __reduce_add_sync(0xffffffffu, _p); \
    _a1 = __reduce_add_sync(0xffffffffu, _a1); \
    if (lane == 0) { wsum2[warp] = _p; wsum[warp] = _a1; } \
    __syncthreads(); \
    if (warp == 0) { \
        int _tp = (lane < 16) ? wsum2[lane] : 0; \
        int _t1 = (lane < 16) ? wsum[lane] : 0; \
        _tp = __reduce_add_sync(0xffffffffu, _tp); \
        _t1 = __reduce_add_sync(0xffffffffu, _t1); \
        if (lane == 0) { s_ge2 = _tp; s_ge = _t1; } \
    } \
    __syncthreads(); \
    c3r = s_ge2 >> 16; c2r = s_ge2 & 0xFFFF; c1r = s_ge; }

#define PAIR_ROUND(bb) { \
    unsigned long long q3 = prefix | (3ull << (bb)); \
    unsigned long long q2 = prefix | (2ull << (bb)); \
    unsigned long long q1 = prefix | (1ull << (bb)); \
    int c3, c2, c1; COUNT3(q3, q2, q1, c3, c2, c1); \
    if      (c3 >= K) prefix = q3; \
    else if (c2 >= K) prefix = q2; \
    else if (c1 >= K) prefix = q1; }

    unsigned long long prefix = 0ull;
    {   // bit 62 alone
        unsigned long long trial = 1ull << 62;
        int c; COUNT_GE(trial, c);
        if (c >= K) prefix = trial;
    }
    // bits 61..32 as 15 pairs
    for (int bb = 60; bb >= 32; bb -= 2) PAIR_ROUND(bb);

    // abs part resolved; exact-K check skips tie-break (no abs ties in practice)
    int c0; COUNT_GE(prefix, c0);
    if (c0 != K) {
        prefix |= 0xFFFFC000ull;            // constant bits 31..14 of every real key
        for (int bb = 12; bb >= 0; bb -= 2) PAIR_ROUND(bb);
    }

#pragma unroll
    for (int r = 0; r < TK_R; r++) {
        if (keys[r] >= prefix) {
            int p = atomicAdd(&scnt, 1);
            if (p < K) cand[p] = keys[r];
        }
    }
    __syncthreads();

    // bitonic sort 512, descending
    for (int sz = 2; sz <= K; sz <<= 1) {
        for (int j = sz >> 1; j > 0; j >>= 1) {
            int ixj = tid ^ j;
            if (ixj > tid) {
                unsigned long long av = cand[tid], bv = cand[ixj];
                bool desc = ((tid & sz) == 0);
                if (desc ? (av < bv) : (av > bv)) { cand[tid] = bv; cand[ixj] = av; }
            }
            __syncthreads();
        }
    }

    unsigned long long key = cand[tid];
    unsigned int hi  = (unsigned int)(key >> 32);
    unsigned int idx = ~(unsigned int)key;
    int   active = (hi != 0u) ? 1 : 0;
    float v   = active ? xrow[idx] : 0.0f;
    int   fid = active ? (int)idx + 1 : 0;

    int nact  = __syncthreads_count(active);
    int empty = (nact == 0) ? 1 : 0;

    // ---- fused closed-form LN stats for this token ----
    float ps = g_SG[NT-1];
#pragma unroll
    for (int k = NT-2; k >= 0; k--) ps = fmaf(ps, v, g_SG[k]);
    float sumh = g_Se[fid] + ps;

    const float4* D4 = (const float4*)&g_D[fid * NT];
    float4 d0 = D4[0], d1 = D4[1];
    float D[NT] = {d0.x, d0.y, d0.z, d0.w, d1.x, d1.y, d1.z, d1.w};
    float pd = D[NT-1];
#pragma unroll
    for (int k = NT-2; k >= 0; k--) pd = fmaf(pd, v, D[k]);
    float pq = g_Q[QN-1];
#pragma unroll
    for (int m = QN-2; m >= 0; m--) pq = fmaf(pq, v, g_Q[m]);
    float sumh2 = g_Se2[fid] + 2.0f*pd + pq;

    float mu   = sumh * (1.0f / H);
    float var  = sumh2 * (1.0f / H) - mu * mu;
    float rstd = rsqrtf(var + 1e-5f);

    unsigned int enc = (unsigned int)fid;
    if (tid == 0 && empty) enc |= 0x80000000u;
    g_tok[b*K + tid] = make_float4(v, __uint_as_float(enc), mu, rstd);

    if (write_mask) {
        float m = (float)active;
        if (tid == 0 && empty) m = 1.0f;
        out[(size_t)TOK * H + (size_t)b * K + tid] = m;
    }
}

// ---------------- kernel 3: fused gather + poly + LN (reduction-free, float4) ----
#define FU_TPB 64
__global__ void __launch_bounds__(192, 5) fuse_kernel(const float* __restrict__ emb,
                                                      const float* __restrict__ lnw,
                                                      const float* __restrict__ lnb,
                                                      float* __restrict__ out) {
    int dg = threadIdx.x;                   // 0..191 -> dims 4*dg..4*dg+3
    float4 G[NT];
#pragma unroll
    for (int k = 0; k < NT; k++) G[k] = ((const float4*)g_G)[k*192 + dg];
    float4 lw = ((const float4*)lnw)[dg];
    float4 lb = ((const float4*)lnb)[dg];
    const float4* emb4 = (const float4*)emb;
    float4* out4 = (float4*)out;

    int t0 = blockIdx.x * FU_TPB;
    for (int tt = t0; tt < t0 + FU_TPB; tt += 4) {
#pragma unroll
        for (int j = 0; j < 4; j++) {
            int tok = tt + j;
            float4 t = g_tok[tok];
            int enc = __float_as_int(t.y);
            float4 e = __ldg(&emb4[(size_t)(enc & 0x7fffffff) * 192 + dg]);
            float v = t.x, mu = t.z, rstd = t.w;
            float px = G[NT-1].x, py = G[NT-1].y, pz = G[NT-1].z, pw = G[NT-1].w;
#pragma unroll
            for (int k = NT-2; k >= 0; k--) {
                px = fmaf(px, v, G[k].x);
                py = fmaf(py, v, G[k].y);
                pz = fmaf(pz, v, G[k].z);
                pw = fmaf(pw, v, G[k].w);
            }
            float4 o;
            o.x = fmaf((e.x + px - mu) * rstd, lw.x, lb.x);
            o.y = fmaf((e.y + py - mu) * rstd, lw.y, lb.y);
            o.z = fmaf((e.z + pz - mu) * rstd, lw.z, lb.z);
            o.w = fmaf((e.w + pw - mu) * rstd, lw.w, lb.w);
            if (enc < 0) { o.x = 0.0f; o.y = 0.0f; o.z = 0.0f; o.w = 0.0f; }
            __stcs(&out4[(size_t)tok * 192 + dg], o);
        }
    }
}

// ---------------- launch --------------------------------------------------------
extern "C" void kernel_launch(void* const* d_in, const int* in_sizes, int n_in,
                              void* d_out, int out_size) {
    const float* x   = (const float*)d_in[0];
    const float* emb = (const float*)d_in[1];
    const float* w1  = (const float*)d_in[2];
    const float* b1  = (const float*)d_in[3];
    const float* w2  = (const float*)d_in[4];
    const float* b2  = (const float*)d_in[5];
    const float* lnw = (const float*)d_in[6];
    const float* lnb = (const float*)d_in[7];
    float* out = (float*)d_out;

    int write_mask = (out_size >= TOK * H + TOK) ? 1 : 0;

    zero_G_kernel<<<6, 1024>>>();
    gvec_kernel<<<dim3(H/128, GV_HB), 128>>>(w1, b1, w2, b2);
    poly_stats_kernel<<<1, H>>>();
    emb_stats_kernel<<<640, 256>>>(emb);
    topk_kernel<<<B, TK_T>>>(x, out, write_mask);
    fuse_kernel<<<TOK/FU_TPB, 192>>>(emb, lnw, lnb, out);
}

// round 9
// speedup vs baseline: 1.7101x; 1.7101x over previous
#include <cuda_runtime.h>
#include <math.h>

#define B   256
#define NF  10000
#define H   768
#define K   512
#define NT  8
#define QN  (2*NT-1)
#define TOK (B*K)

// ---------------- scratch ----------------
__device__ __align__(16) float g_G[NT*H];
__device__ float g_SG[NT];
__device__ float g_Q[QN];
__device__ float g_Se[NF+1];
__device__ float g_Se2[NF+1];
__device__ __align__(16) float g_D[(NF+1)*NT];
__device__ float4 g_tok[TOK];

// ---------------- kernel 0: zero g_G for gvec atomics ---------------------------
__global__ void zero_G_kernel() {
    int i = blockIdx.x * 1024 + threadIdx.x;
    if (i < NT*H) g_G[i] = 0.0f;
}

// ---------------- kernel 1: G_k = w2^T c_k (+ b2 into k=0) ----------------------
// Taylor coefficients of gelu(w1[h]*v + b1[h]) computed inline in fp32 per block.
#define GV_HB 32
#define GV_HC (H / GV_HB)
__global__ void gvec_kernel(const float* __restrict__ w1, const float* __restrict__ b1,
                            const float* __restrict__ w2, const float* __restrict__ b2) {
    __shared__ float sc[NT * GV_HC];
    int tid = threadIdx.x;                  // 128
    int d   = blockIdx.x * 128 + tid;
    int h0  = blockIdx.y * GV_HC;

    if (tid < GV_HC) {
        int h = h0 + tid;
        float a    = w1[h];
        float beta = b1[h];
        float phi = 0.3989422804f * expf(-0.5f * beta * beta);
        float Phi = 0.5f * (1.0f + erff(beta * 0.7071067812f));
        sc[0*GV_HC + tid] = beta * Phi;                 // gelu(beta)
        sc[1*GV_HC + tid] = (Phi + beta * phi) * a;     // gelu'(beta)*a
        float He_km2 = 1.0f, He_km1 = beta, fact = 1.0f, apow = a;
#pragma unroll
        for (int k = 2; k < NT; k++) {
            fact *= (float)k;
            apow *= a;
            float s  = (k & 1) ? -1.0f : 1.0f;
            float gk = phi * s * ((float)k * He_km2 - beta * He_km1);
            sc[k*GV_HC + tid] = gk * apow / fact;
            float He_k = beta * He_km1 - (float)(k - 1) * He_km2;
            He_km2 = He_km1; He_km1 = He_k;
        }
    }
    __syncthreads();

    float acc[NT];
#pragma unroll
    for (int k = 0; k < NT; k++) acc[k] = 0.0f;
#pragma unroll 4
    for (int h = 0; h < GV_HC; h++) {
        float w = w2[(size_t)(h0 + h) * H + d];
#pragma unroll
        for (int k = 0; k < NT; k++) acc[k] = fmaf(sc[k*GV_HC + h], w, acc[k]);
    }
    if (blockIdx.y == 0) acc[0] += b2[d];
#pragma unroll
    for (int k = 0; k < NT; k++) atomicAdd(&g_G[k*H + d], acc[k]);
}

// ---------------- kernel 1c: SG_k and Q_m (1 block, 768 threads) -----------------
__global__ void poly_stats_kernel() {
    __shared__ float s[NT + NT*(NT+1)/2];
    int d = threadIdx.x;
    int lane = d & 31;
    if (d < NT + NT*(NT+1)/2) s[d] = 0.0f;
    __syncthreads();
    float g[NT];
#pragma unroll
    for (int k = 0; k < NT; k++) g[k] = g_G[k*H + d];

#define BRED(slot, expr) { float _v = (expr); \
    _v += __shfl_down_sync(0xffffffffu, _v, 16); \
    _v += __shfl_down_sync(0xffffffffu, _v, 8);  \
    _v += __shfl_down_sync(0xffffffffu, _v, 4);  \
    _v += __shfl_down_sync(0xffffffffu, _v, 2);  \
    _v += __shfl_down_sync(0xffffffffu, _v, 1);  \
    if (lane == 0) atomicAdd(&s[slot], _v); }

#pragma unroll
    for (int k = 0; k < NT; k++) BRED(k, g[k]);
    {
        int idx = NT;
#pragma unroll
        for (int k = 0; k < NT; k++)
#pragma unroll
            for (int l = k; l < NT; l++) { BRED(idx, g[k]*g[l]); idx++; }
    }
    __syncthreads();
    if (d == 0) {
        for (int k = 0; k < NT; k++) g_SG[k] = s[k];
        float q[QN];
        for (int m = 0; m < QN; m++) q[m] = 0.0f;
        int idx = NT;
        for (int k = 0; k < NT; k++)
            for (int l = k; l < NT; l++) {
                q[k+l] += (k == l ? 1.0f : 2.0f) * s[idx];
                idx++;
            }
        for (int m = 0; m < QN; m++) g_Q[m] = q[m];
    }
}

// ---------------- kernel 1d: per-emb-row Se, Se2, D_k (warp x 4 rows) ------------
// R7-proven configuration: 4 rows/warp = 24 independent LDG.128 in flight.
__global__ void __launch_bounds__(256, 3) emb_stats_kernel(const float* __restrict__ emb) {
    __shared__ float4 sG[NT * 192];         // 24 KB
    int tid  = threadIdx.x;
    int lane = tid & 31, warp = tid >> 5;   // 8 warps
    const float4* G4 = (const float4*)g_G;
    for (int i = tid; i < NT * 192; i += 256) sG[i] = G4[i];
    __syncthreads();

    int r0 = (blockIdx.x * 8 + warp) * 4;
    if (r0 > NF) return;
    int nrow = NF + 1 - r0; if (nrow > 4) nrow = 4;

    const float4* emb4 = (const float4*)emb;
    float acc[4][NT+2];
#pragma unroll
    for (int t = 0; t < 4; t++)
#pragma unroll
        for (int i = 0; i < NT+2; i++) acc[t][i] = 0.0f;

#pragma unroll
    for (int j = 0; j < 6; j++) {
        int dg = lane + 32*j;
        float4 e[4];
#pragma unroll
        for (int t = 0; t < 4; t++)
            e[t] = (t < nrow) ? __ldg(&emb4[(size_t)(r0 + t) * 192 + dg])
                              : make_float4(0.f, 0.f, 0.f, 0.f);
#pragma unroll
        for (int t = 0; t < 4; t++) {
            acc[t][0] += e[t].x + e[t].y + e[t].z + e[t].w;
            acc[t][1] += e[t].x*e[t].x + e[t].y*e[t].y + e[t].z*e[t].z + e[t].w*e[t].w;
        }
#pragma unroll
        for (int k = 0; k < NT; k++) {
            float4 g = sG[k*192 + dg];
#pragma unroll
            for (int t = 0; t < 4; t++)
                acc[t][2+k] += e[t].x*g.x + e[t].y*g.y + e[t].z*g.z + e[t].w*g.w;
        }
    }
#pragma unroll
    for (int t = 0; t < 4; t++)
#pragma unroll
        for (int i = 0; i < NT+2; i++) {
            float v = acc[t][i];
            v += __shfl_down_sync(0xffffffffu, v, 16);
            v += __shfl_down_sync(0xffffffffu, v, 8);
            v += __shfl_down_sync(0xffffffffu, v, 4);
            v += __shfl_down_sync(0xffffffffu, v, 2);
            v += __shfl_down_sync(0xffffffffu, v, 1);
            acc[t][i] = v;
        }
    if (lane == 0) {
        for (int t = 0; t < nrow; t++) {
            int r = r0 + t;
            g_Se[r]  = acc[t][0];
            g_Se2[r] = acc[t][1];
            float4* D4 = (float4*)&g_D[r * NT];
            D4[0] = make_float4(acc[t][2], acc[t][3], acc[t][4], acc[t][5]);
            D4[1] = make_float4(acc[t][6], acc[t][7], acc[t][8], acc[t][9]);
        }
    }
}

// ---------------- kernel 2: top-512 + fused closed-form LN stats -----------------
// key = (abs_bits<<32) | ~idx. Bits 63, 31..14 constant across real keys.
// R7-proven single-bit rounds; accepted-prefix count tracked to skip the extra
// early-exit COUNT.
#define TK_T 512
#define TK_R 20      // 512*20 = 10240 >= NF
__global__ void __launch_bounds__(TK_T, 2) topk_kernel(const float* __restrict__ x,
                                                       float* __restrict__ out,
                                                       int write_mask) {
    __shared__ float xrow[NF];
    __shared__ unsigned long long cand[K];
    __shared__ int wsum[16];
    __shared__ int s_ge;
    __shared__ int scnt;

    int b    = blockIdx.x;
    int tid  = threadIdx.x;
    int lane = tid & 31, warp = tid >> 5;
    const float4* xr4 = (const float4*)(x + (size_t)b * NF);
    for (int i = tid; i < NF/4; i += TK_T) ((float4*)xrow)[i] = xr4[i];
    if (tid == 0) scnt = 0;
    __syncthreads();

    unsigned long long keys[TK_R];
#pragma unroll
    for (int r = 0; r < TK_R; r++) {
        int i = tid + r * TK_T;
        unsigned long long kb = 0ull;
        if (i < NF) {
            unsigned int ab = __float_as_uint(fabsf(xrow[i]));
            kb = ((unsigned long long)ab << 32) | (unsigned int)(~i);
        }
        keys[r] = kb;
    }

#define COUNT_GE(trial, res) { \
    int _c = 0; \
    _Pragma("unroll") \
    for (int _r = 0; _r < TK_R; _r++) _c += (keys[_r] >= (trial)) ? 1 : 0; \
    _c = __reduce_add_sync(0xffffffffu, _c); \
    if (lane == 0) wsum[warp] = _c; \
    __syncthreads(); \
    if (warp == 0) { \
        int _t = (lane < 16) ? wsum[lane] : 0; \
        _t = __reduce_add_sync(0xffffffffu, _t); \
        if (lane == 0) s_ge = _t; \
    } \
    __syncthreads(); \
    res = s_ge; }

    unsigned long long prefix = 0ull;
    int cbest = TK_T * TK_R;                // count of keys >= 0 (all)
    for (int bit = 62; bit >= 32; bit--) {
        unsigned long long trial = prefix | (1ull << bit);
        int c; COUNT_GE(trial, c);
        if (c >= K) { prefix = trial; cbest = c; }
    }
    // abs part resolved; if the accepted-prefix count is exactly K (no abs ties,
    // the statistically certain case) the 14 tie-break rounds are unnecessary.
    if (cbest != K) {
        prefix |= 0xFFFFC000ull;            // constant bits 31..14 of every real key
        for (int bit = 13; bit >= 0; bit--) {
            unsigned long long trial = prefix | (1ull << bit);
            int c; COUNT_GE(trial, c);
            if (c >= K) prefix = trial;
        }
    }

#pragma unroll
    for (int r = 0; r < TK_R; r++) {
        if (keys[r] >= prefix) {
            int p = atomicAdd(&scnt, 1);
            if (p < K) cand[p] = keys[r];
        }
    }
    __syncthreads();

    // bitonic sort 512, descending
    for (int sz = 2; sz <= K; sz <<= 1) {
        for (int j = sz >> 1; j > 0; j >>= 1) {
            int ixj = tid ^ j;
            if (ixj > tid) {
                unsigned long long av = cand[tid], bv = cand[ixj];
                bool desc = ((tid & sz) == 0);
                if (desc ? (av < bv) : (av > bv)) { cand[tid] = bv; cand[ixj] = av; }
            }
            __syncthreads();
        }
    }

    unsigned long long key = cand[tid];
    unsigned int hi  = (unsigned int)(key >> 32);
    unsigned int idx = ~(unsigned int)key;
    int   active = (hi != 0u) ? 1 : 0;
    float v   = active ? xrow[idx] : 0.0f;
    int   fid = active ? (int)idx + 1 : 0;

    int nact  = __syncthreads_count(active);
    int empty = (nact == 0) ? 1 : 0;

    // ---- fused closed-form LN stats for this token ----
    float ps = g_SG[NT-1];
#pragma unroll
    for (int k = NT-2; k >= 0; k--) ps = fmaf(ps, v, g_SG[k]);
    float sumh = g_Se[fid] + ps;

    const float4* D4 = (const float4*)&g_D[fid * NT];
    float4 d0 = D4[0], d1 = D4[1];
    float D[NT] = {d0.x, d0.y, d0.z, d0.w, d1.x, d1.y, d1.z, d1.w};
    float pd = D[NT-1];
#pragma unroll
    for (int k = NT-2; k >= 0; k--) pd = fmaf(pd, v, D[k]);
    float pq = g_Q[QN-1];
#pragma unroll
    for (int m = QN-2; m >= 0; m--) pq = fmaf(pq, v, g_Q[m]);
    float sumh2 = g_Se2[fid] + 2.0f*pd + pq;

    float mu   = sumh * (1.0f / H);
    float var  = sumh2 * (1.0f / H) - mu * mu;
    float rstd = rsqrtf(var + 1e-5f);

    unsigned int enc = (unsigned int)fid;
    if (tid == 0 && empty) enc |= 0x80000000u;
    g_tok[b*K + tid] = make_float4(v, __uint_as_float(enc), mu, rstd);

    if (write_mask) {
        float m = (float)active;
        if (tid == 0 && empty) m = 1.0f;
        out[(size_t)TOK * H + (size_t)b * K + tid] = m;
    }
}

// ---------------- kernel 3: fused gather + poly + LN (reduction-free, float4) ----
#define FU_TPB 64
__global__ void __launch_bounds__(192, 5) fuse_kernel(const float* __restrict__ emb,
                                                      const float* __restrict__ lnw,
                                                      const float* __restrict__ lnb,
                                                      float* __restrict__ out) {
    int dg = threadIdx.x;                   // 0..191 -> dims 4*dg..4*dg+3
    float4 G[NT];
#pragma unroll
    for (int k = 0; k < NT; k++) G[k] = ((const float4*)g_G)[k*192 + dg];
    float4 lw = ((const float4*)lnw)[dg];
    float4 lb = ((const float4*)lnb)[dg];
    const float4* emb4 = (const float4*)emb;
    float4* out4 = (float4*)out;

    int t0 = blockIdx.x * FU_TPB;
    for (int tt = t0; tt < t0 + FU_TPB; tt += 4) {
#pragma unroll
        for (int j = 0; j < 4; j++) {
            int tok = tt + j;
            float4 t = g_tok[tok];
            int enc = __float_as_int(t.y);
            float4 e = __ldg(&emb4[(size_t)(enc & 0x7fffffff) * 192 + dg]);
            float v = t.x, mu = t.z, rstd = t.w;
            float px = G[NT-1].x, py = G[NT-1].y, pz = G[NT-1].z, pw = G[NT-1].w;
#pragma unroll
            for (int k = NT-2; k >= 0; k--) {
                px = fmaf(px, v, G[k].x);
                py = fmaf(py, v, G[k].y);
                pz = fmaf(pz, v, G[k].z);
                pw = fmaf(pw, v, G[k].w);
            }
            float4 o;
            o.x = fmaf((e.x + px - mu) * rstd, lw.x, lb.x);
            o.y = fmaf((e.y + py - mu) * rstd, lw.y, lb.y);
            o.z = fmaf((e.z + pz - mu) * rstd, lw.z, lb.z);
            o.w = fmaf((e.w + pw - mu) * rstd, lw.w, lb.w);
            if (enc < 0) { o.x = 0.0f; o.y = 0.0f; o.z = 0.0f; o.w = 0.0f; }
            __stcs(&out4[(size_t)tok * 192 + dg], o);
        }
    }
}

// ---------------- launch --------------------------------------------------------
extern "C" void kernel_launch(void* const* d_in, const int* in_sizes, int n_in,
                              void* d_out, int out_size) {
    const float* x   = (const float*)d_in[0];
    const float* emb = (const float*)d_in[1];
    const float* w1  = (const float*)d_in[2];
    const float* b1  = (const float*)d_in[3];
    const float* w2  = (const float*)d_in[4];
    const float* b2  = (const float*)d_in[5];
    const float* lnw = (const float*)d_in[6];
    const float* lnb = (const float*)d_in[7];
    float* out = (float*)d_out;

    int write_mask = (out_size >= TOK * H + TOK) ? 1 : 0;

    zero_G_kernel<<<6, 1024>>>();
    gvec_kernel<<<dim3(H/128, GV_HB), 128>>>(w1, b1, w2, b2);
    poly_stats_kernel<<<1, H>>>();
    emb_stats_kernel<<<313, 256>>>(emb);
    topk_kernel<<<B, TK_T>>>(x, out, write_mask);
    fuse_kernel<<<TOK/FU_TPB, 192>>>(emb, lnw, lnb, out);
}

// round 10
// speedup vs baseline: 1.7324x; 1.0131x over previous
#include <cuda_runtime.h>
#include <math.h>

#define B   256
#define NF  10000
#define H   768
#define K   512
#define NT  8
#define QN  (2*NT-1)
#define TOK (B*K)

typedef unsigned long long u64;
__device__ __forceinline__ u64 pk2(float lo, float hi) {
    u64 r; asm("mov.b64 %0, {%1, %2};" : "=l"(r) : "f"(lo), "f"(hi)); return r;
}
__device__ __forceinline__ void upk2(u64 v, float& lo, float& hi) {
    asm("mov.b64 {%0, %1}, %2;" : "=f"(lo), "=f"(hi) : "l"(v));
}
__device__ __forceinline__ u64 fma2(u64 a, u64 b, u64 c) {
    u64 d; asm("fma.rn.f32x2 %0, %1, %2, %3;" : "=l"(d) : "l"(a), "l"(b), "l"(c)); return d;
}
__device__ __forceinline__ u64 add2(u64 a, u64 b) {
    u64 d; asm("add.rn.f32x2 %0, %1, %2;" : "=l"(d) : "l"(a), "l"(b)); return d;
}

// ---------------- scratch ----------------
__device__ __align__(16) float g_G[NT*H];
__device__ float g_SG[NT];
__device__ float g_Q[QN];
__device__ float g_Se[NF+1];
__device__ float g_Se2[NF+1];
__device__ __align__(16) float g_D[(NF+1)*NT];
__device__ float4 g_tok[TOK];

// ---------------- kernel 0: zero g_G for gvec atomics ---------------------------
__global__ void zero_G_kernel() {
    int i = blockIdx.x * 1024 + threadIdx.x;
    if (i < NT*H) g_G[i] = 0.0f;
}

// ---------------- kernel 1: G_k = w2^T c_k (+ b2 into k=0) ----------------------
#define GV_HB 32
#define GV_HC (H / GV_HB)
__global__ void gvec_kernel(const float* __restrict__ w1, const float* __restrict__ b1,
                            const float* __restrict__ w2, const float* __restrict__ b2) {
    __shared__ float sc[NT * GV_HC];
    int tid = threadIdx.x;                  // 128
    int d   = blockIdx.x * 128 + tid;
    int h0  = blockIdx.y * GV_HC;

    if (tid < GV_HC) {
        int h = h0 + tid;
        float a    = w1[h];
        float beta = b1[h];
        float phi = 0.3989422804f * expf(-0.5f * beta * beta);
        float Phi = 0.5f * (1.0f + erff(beta * 0.7071067812f));
        sc[0*GV_HC + tid] = beta * Phi;                 // gelu(beta)
        sc[1*GV_HC + tid] = (Phi + beta * phi) * a;     // gelu'(beta)*a
        float He_km2 = 1.0f, He_km1 = beta, fact = 1.0f, apow = a;
#pragma unroll
        for (int k = 2; k < NT; k++) {
            fact *= (float)k;
            apow *= a;
            float s  = (k & 1) ? -1.0f : 1.0f;
            float gk = phi * s * ((float)k * He_km2 - beta * He_km1);
            sc[k*GV_HC + tid] = gk * apow / fact;
            float He_k = beta * He_km1 - (float)(k - 1) * He_km2;
            He_km2 = He_km1; He_km1 = He_k;
        }
    }
    __syncthreads();

    float acc[NT];
#pragma unroll
    for (int k = 0; k < NT; k++) acc[k] = 0.0f;
#pragma unroll 4
    for (int h = 0; h < GV_HC; h++) {
        float w = w2[(size_t)(h0 + h) * H + d];
#pragma unroll
        for (int k = 0; k < NT; k++) acc[k] = fmaf(sc[k*GV_HC + h], w, acc[k]);
    }
    if (blockIdx.y == 0) acc[0] += b2[d];
#pragma unroll
    for (int k = 0; k < NT; k++) atomicAdd(&g_G[k*H + d], acc[k]);
}

// ---------------- kernel 1c: SG_k and Q_m (1 block, 768 threads) -----------------
__global__ void poly_stats_kernel() {
    __shared__ float s[NT + NT*(NT+1)/2];
    int d = threadIdx.x;
    int lane = d & 31;
    if (d < NT + NT*(NT+1)/2) s[d] = 0.0f;
    __syncthreads();
    float g[NT];
#pragma unroll
    for (int k = 0; k < NT; k++) g[k] = g_G[k*H + d];

#define BRED(slot, expr) { float _v = (expr); \
    _v += __shfl_down_sync(0xffffffffu, _v, 16); \
    _v += __shfl_down_sync(0xffffffffu, _v, 8);  \
    _v += __shfl_down_sync(0xffffffffu, _v, 4);  \
    _v += __shfl_down_sync(0xffffffffu, _v, 2);  \
    _v += __shfl_down_sync(0xffffffffu, _v, 1);  \
    if (lane == 0) atomicAdd(&s[slot], _v); }

#pragma unroll
    for (int k = 0; k < NT; k++) BRED(k, g[k]);
    {
        int idx = NT;
#pragma unroll
        for (int k = 0; k < NT; k++)
#pragma unroll
            for (int l = k; l < NT; l++) { BRED(idx, g[k]*g[l]); idx++; }
    }
    __syncthreads();
    if (d == 0) {
        for (int k = 0; k < NT; k++) g_SG[k] = s[k];
        float q[QN];
        for (int m = 0; m < QN; m++) q[m] = 0.0f;
        int idx = NT;
        for (int k = 0; k < NT; k++)
            for (int l = k; l < NT; l++) {
                q[k+l] += (k == l ? 1.0f : 2.0f) * s[idx];
                idx++;
            }
        for (int m = 0; m < QN; m++) g_Q[m] = q[m];
    }
}

// ---------------- kernel 1d: per-emb-row Se, Se2, D_k (warp x 4 rows) ------------
// R7-proven configuration: 4 rows/warp = 24 independent LDG.128 in flight.
__global__ void __launch_bounds__(256, 3) emb_stats_kernel(const float* __restrict__ emb) {
    __shared__ float4 sG[NT * 192];         // 24 KB
    int tid  = threadIdx.x;
    int lane = tid & 31, warp = tid >> 5;   // 8 warps
    const float4* G4 = (const float4*)g_G;
    for (int i = tid; i < NT * 192; i += 256) sG[i] = G4[i];
    __syncthreads();

    int r0 = (blockIdx.x * 8 + warp) * 4;
    if (r0 > NF) return;
    int nrow = NF + 1 - r0; if (nrow > 4) nrow = 4;

    const float4* emb4 = (const float4*)emb;
    float acc[4][NT+2];
#pragma unroll
    for (int t = 0; t < 4; t++)
#pragma unroll
        for (int i = 0; i < NT+2; i++) acc[t][i] = 0.0f;

#pragma unroll
    for (int j = 0; j < 6; j++) {
        int dg = lane + 32*j;
        float4 e[4];
#pragma unroll
        for (int t = 0; t < 4; t++)
            e[t] = (t < nrow) ? __ldg(&emb4[(size_t)(r0 + t) * 192 + dg])
                              : make_float4(0.f, 0.f, 0.f, 0.f);
#pragma unroll
        for (int t = 0; t < 4; t++) {
            acc[t][0] += e[t].x + e[t].y + e[t].z + e[t].w;
            acc[t][1] += e[t].x*e[t].x + e[t].y*e[t].y + e[t].z*e[t].z + e[t].w*e[t].w;
        }
#pragma unroll
        for (int k = 0; k < NT; k++) {
            float4 g = sG[k*192 + dg];
#pragma unroll
            for (int t = 0; t < 4; t++)
                acc[t][2+k] += e[t].x*g.x + e[t].y*g.y + e[t].z*g.z + e[t].w*g.w;
        }
    }
#pragma unroll
    for (int t = 0; t < 4; t++)
#pragma unroll
        for (int i = 0; i < NT+2; i++) {
            float v = acc[t][i];
            v += __shfl_down_sync(0xffffffffu, v, 16);
            v += __shfl_down_sync(0xffffffffu, v, 8);
            v += __shfl_down_sync(0xffffffffu, v, 4);
            v += __shfl_down_sync(0xffffffffu, v, 2);
            v += __shfl_down_sync(0xffffffffu, v, 1);
            acc[t][i] = v;
        }
    if (lane == 0) {
        for (int t = 0; t < nrow; t++) {
            int r = r0 + t;
            g_Se[r]  = acc[t][0];
            g_Se2[r] = acc[t][1];
            float4* D4 = (float4*)&g_D[r * NT];
            D4[0] = make_float4(acc[t][2], acc[t][3], acc[t][4], acc[t][5]);
            D4[1] = make_float4(acc[t][6], acc[t][7], acc[t][8], acc[t][9]);
        }
    }
}

// ---------------- kernel 2: top-512 + fused closed-form LN stats -----------------
#define TK_T 512
#define TK_R 20      // 512*20 = 10240 >= NF
__global__ void __launch_bounds__(TK_T, 2) topk_kernel(const float* __restrict__ x,
                                                       float* __restrict__ out,
                                                       int write_mask) {
    __shared__ float xrow[NF];
    __shared__ unsigned long long cand[K];
    __shared__ int wsum[16];
    __shared__ int s_ge;
    __shared__ int scnt;

    int b    = blockIdx.x;
    int tid  = threadIdx.x;
    int lane = tid & 31, warp = tid >> 5;
    const float4* xr4 = (const float4*)(x + (size_t)b * NF);
    for (int i = tid; i < NF/4; i += TK_T) ((float4*)xrow)[i] = xr4[i];
    if (tid == 0) scnt = 0;
    __syncthreads();

    unsigned long long keys[TK_R];
#pragma unroll
    for (int r = 0; r < TK_R; r++) {
        int i = tid + r * TK_T;
        unsigned long long kb = 0ull;
        if (i < NF) {
            unsigned int ab = __float_as_uint(fabsf(xrow[i]));
            kb = ((unsigned long long)ab << 32) | (unsigned int)(~i);
        }
        keys[r] = kb;
    }

#define COUNT_GE(trial, res) { \
    int _c = 0; \
    _Pragma("unroll") \
    for (int _r = 0; _r < TK_R; _r++) _c += (keys[_r] >= (trial)) ? 1 : 0; \
    _c = __reduce_add_sync(0xffffffffu, _c); \
    if (lane == 0) wsum[warp] = _c; \
    __syncthreads(); \
    if (warp == 0) { \
        int _t = (lane < 16) ? wsum[lane] : 0; \
        _t = __reduce_add_sync(0xffffffffu, _t); \
        if (lane == 0) s_ge = _t; \
    } \
    __syncthreads(); \
    res = s_ge; }

    unsigned long long prefix = 0ull;
    int cbest = TK_T * TK_R;
    for (int bit = 62; bit >= 32; bit--) {
        unsigned long long trial = prefix | (1ull << bit);
        int c; COUNT_GE(trial, c);
        if (c >= K) { prefix = trial; cbest = c; }
    }
    if (cbest != K) {
        prefix |= 0xFFFFC000ull;            // constant bits 31..14 of every real key
        for (int bit = 13; bit >= 0; bit--) {
            unsigned long long trial = prefix | (1ull << bit);
            int c; COUNT_GE(trial, c);
            if (c >= K) prefix = trial;
        }
    }

#pragma unroll
    for (int r = 0; r < TK_R; r++) {
        if (keys[r] >= prefix) {
            int p = atomicAdd(&scnt, 1);
            if (p < K) cand[p] = keys[r];
        }
    }
    __syncthreads();

    // bitonic sort 512, descending
    for (int sz = 2; sz <= K; sz <<= 1) {
        for (int j = sz >> 1; j > 0; j >>= 1) {
            int ixj = tid ^ j;
            if (ixj > tid) {
                unsigned long long av = cand[tid], bv = cand[ixj];
                bool desc = ((tid & sz) == 0);
                if (desc ? (av < bv) : (av > bv)) { cand[tid] = bv; cand[ixj] = av; }
            }
            __syncthreads();
        }
    }

    unsigned long long key = cand[tid];
    unsigned int hi  = (unsigned int)(key >> 32);
    unsigned int idx = ~(unsigned int)key;
    int   active = (hi != 0u) ? 1 : 0;
    float v   = active ? xrow[idx] : 0.0f;
    int   fid = active ? (int)idx + 1 : 0;

    int nact  = __syncthreads_count(active);
    int empty = (nact == 0) ? 1 : 0;

    // ---- fused closed-form LN stats for this token ----
    float ps = g_SG[NT-1];
#pragma unroll
    for (int k = NT-2; k >= 0; k--) ps = fmaf(ps, v, g_SG[k]);
    float sumh = g_Se[fid] + ps;

    const float4* D4 = (const float4*)&g_D[fid * NT];
    float4 d0 = D4[0], d1 = D4[1];
    float D[NT] = {d0.x, d0.y, d0.z, d0.w, d1.x, d1.y, d1.z, d1.w};
    float pd = D[NT-1];
#pragma unroll
    for (int k = NT-2; k >= 0; k--) pd = fmaf(pd, v, D[k]);
    float pq = g_Q[QN-1];
#pragma unroll
    for (int m = QN-2; m >= 0; m--) pq = fmaf(pq, v, g_Q[m]);
    float sumh2 = g_Se2[fid] + 2.0f*pd + pq;

    float mu   = sumh * (1.0f / H);
    float var  = sumh2 * (1.0f / H) - mu * mu;
    float rstd = rsqrtf(var + 1e-5f);

    unsigned int enc = (unsigned int)fid;
    if (tid == 0 && empty) enc |= 0x80000000u;
    g_tok[b*K + tid] = make_float4(v, __uint_as_float(enc), mu, rstd);

    if (write_mask) {
        float m = (float)active;
        if (tid == 0 && empty) m = 1.0f;
        out[(size_t)TOK * H + (size_t)b * K + tid] = m;
    }
}

// ---------------- kernel 3: fused gather + poly + LN (f32x2 packed math) ---------
#define FU_TPB 64
__global__ void __launch_bounds__(192, 5) fuse_kernel(const float* __restrict__ emb,
                                                      const float* __restrict__ lnw,
                                                      const float* __restrict__ lnb,
                                                      float* __restrict__ out) {
    int dg = threadIdx.x;                   // 0..191 -> dims 4*dg..4*dg+3
    u64 Gxy[NT], Gzw[NT];
#pragma unroll
    for (int k = 0; k < NT; k++) {
        float4 g = ((const float4*)g_G)[k*192 + dg];
        Gxy[k] = pk2(g.x, g.y);
        Gzw[k] = pk2(g.z, g.w);
    }
    float4 lwf = ((const float4*)lnw)[dg];
    float4 lbf = ((const float4*)lnb)[dg];
    u64 lwxy = pk2(lwf.x, lwf.y), lwzw = pk2(lwf.z, lwf.w);
    u64 lbxy = pk2(lbf.x, lbf.y), lbzw = pk2(lbf.z, lbf.w);
    const float4* emb4 = (const float4*)emb;
    float4* out4 = (float4*)out;

    int t0 = blockIdx.x * FU_TPB;
    for (int tt = t0; tt < t0 + FU_TPB; tt += 4) {
#pragma unroll
        for (int j = 0; j < 4; j++) {
            int tok = tt + j;
            float4 t = g_tok[tok];
            int enc = __float_as_int(t.y);
            float4 e = __ldg(&emb4[(size_t)(enc & 0x7fffffff) * 192 + dg]);
            float v = t.x, mu = t.z, rstd = t.w;

            u64 vv = pk2(v, v);
            u64 rr = pk2(rstd, rstd);
            float nmr = -mu * rstd;
            u64 mm = pk2(nmr, nmr);

            u64 pxy = Gxy[NT-1], pzw = Gzw[NT-1];
#pragma unroll
            for (int k = NT-2; k >= 0; k--) {
                pxy = fma2(pxy, vv, Gxy[k]);
                pzw = fma2(pzw, vv, Gzw[k]);
            }
            u64 hxy = add2(pk2(e.x, e.y), pxy);
            u64 hzw = add2(pk2(e.z, e.w), pzw);
            u64 txy = fma2(hxy, rr, mm);
            u64 tzw = fma2(hzw, rr, mm);
            u64 oxy = fma2(txy, lwxy, lbxy);
            u64 ozw = fma2(tzw, lwzw, lbzw);

            float4 o;
            upk2(oxy, o.x, o.y);
            upk2(ozw, o.z, o.w);
            if (enc < 0) { o.x = 0.0f; o.y = 0.0f; o.z = 0.0f; o.w = 0.0f; }
            __stcs(&out4[(size_t)tok * 192 + dg], o);
        }
    }
}

// ---------------- launch --------------------------------------------------------
extern "C" void kernel_launch(void* const* d_in, const int* in_sizes, int n_in,
                              void* d_out, int out_size) {
    const float* x   = (const float*)d_in[0];
    const float* emb = (const float*)d_in[1];
    const float* w1  = (const float*)d_in[2];
    const float* b1  = (const float*)d_in[3];
    const float* w2  = (const float*)d_in[4];
    const float* b2  = (const float*)d_in[5];
    const float* lnw = (const float*)d_in[6];
    const float* lnb = (const float*)d_in[7];
    float* out = (float*)d_out;

    int write_mask = (out_size >= TOK * H + TOK) ? 1 : 0;

    zero_G_kernel<<<6, 1024>>>();
    gvec_kernel<<<dim3(H/128, GV_HB), 128>>>(w1, b1, w2, b2);
    poly_stats_kernel<<<1, H>>>();
    emb_stats_kernel<<<313, 256>>>(emb);
    topk_kernel<<<B, TK_T>>>(x, out, write_mask);
    fuse_kernel<<<TOK/FU_TPB, 192>>>(emb, lnw, lnb, out);
}

// round 12
// speedup vs baseline: 1.7565x; 1.0139x over previous
#include <cuda_runtime.h>
#include <math.h>

#define B   256
#define NF  10000
#define H   768
#define K   512
#define NT  8
#define QN  (2*NT-1)
#define TOK (B*K)

typedef unsigned long long u64;
__device__ __forceinline__ u64 pk2(float lo, float hi) {
    u64 r; asm("mov.b64 %0, {%1, %2};" : "=l"(r) : "f"(lo), "f"(hi)); return r;
}
__device__ __forceinline__ void upk2(u64 v, float& lo, float& hi) {
    asm("mov.b64 {%0, %1}, %2;" : "=f"(lo), "=f"(hi) : "l"(v));
}
__device__ __forceinline__ u64 fma2(u64 a, u64 b, u64 c) {
    u64 d; asm("fma.rn.f32x2 %0, %1, %2, %3;" : "=l"(d) : "l"(a), "l"(b), "l"(c)); return d;
}
__device__ __forceinline__ u64 add2(u64 a, u64 b) {
    u64 d; asm("add.rn.f32x2 %0, %1, %2;" : "=l"(d) : "l"(a), "l"(b)); return d;
}

// ---------------- scratch ----------------
__device__ __align__(16) float g_G[NT*H];
__device__ float g_SG[NT];
__device__ float g_Q[QN];
__device__ float g_Se[NF+1];
__device__ float g_Se2[NF+1];
__device__ __align__(16) float g_D[(NF+1)*NT];
__device__ float4 g_tok[TOK];

// ---------------- kernel 0: zero g_G for gvec atomics ---------------------------
__global__ void zero_G_kernel() {
    int i = blockIdx.x * 1024 + threadIdx.x;
    if (i < NT*H) g_G[i] = 0.0f;
}

// ---------------- kernel 1: G_k = w2^T c_k (+ b2 into k=0) ----------------------
#define GV_HB 32
#define GV_HC (H / GV_HB)
__global__ void gvec_kernel(const float* __restrict__ w1, const float* __restrict__ b1,
                            const float* __restrict__ w2, const float* __restrict__ b2) {
    __shared__ float sc[NT * GV_HC];
    int tid = threadIdx.x;                  // 128
    int d   = blockIdx.x * 128 + tid;
    int h0  = blockIdx.y * GV_HC;

    if (tid < GV_HC) {
        int h = h0 + tid;
        float a    = w1[h];
        float beta = b1[h];
        float phi = 0.3989422804f * expf(-0.5f * beta * beta);
        float Phi = 0.5f * (1.0f + erff(beta * 0.7071067812f));
        sc[0*GV_HC + tid] = beta * Phi;                 // gelu(beta)
        sc[1*GV_HC + tid] = (Phi + beta * phi) * a;     // gelu'(beta)*a
        float He_km2 = 1.0f, He_km1 = beta, fact = 1.0f, apow = a;
#pragma unroll
        for (int k = 2; k < NT; k++) {
            fact *= (float)k;
            apow *= a;
            float s  = (k & 1) ? -1.0f : 1.0f;
            float gk = phi * s * ((float)k * He_km2 - beta * He_km1);
            sc[k*GV_HC + tid] = gk * apow / fact;
            float He_k = beta * He_km1 - (float)(k - 1) * He_km2;
            He_km2 = He_km1; He_km1 = He_k;
        }
    }
    __syncthreads();

    float acc[NT];
#pragma unroll
    for (int k = 0; k < NT; k++) acc[k] = 0.0f;
#pragma unroll 4
    for (int h = 0; h < GV_HC; h++) {
        float w = w2[(size_t)(h0 + h) * H + d];
#pragma unroll
        for (int k = 0; k < NT; k++) acc[k] = fmaf(sc[k*GV_HC + h], w, acc[k]);
    }
    if (blockIdx.y == 0) acc[0] += b2[d];
#pragma unroll
    for (int k = 0; k < NT; k++) atomicAdd(&g_G[k*H + d], acc[k]);
}

// ---------------- kernel 1c: SG_k and Q_m (1 block, 768 threads) -----------------
__global__ void poly_stats_kernel() {
    __shared__ float s[NT + NT*(NT+1)/2];
    int d = threadIdx.x;
    int lane = d & 31;
    if (d < NT + NT*(NT+1)/2) s[d] = 0.0f;
    __syncthreads();
    float g[NT];
#pragma unroll
    for (int k = 0; k < NT; k++) g[k] = g_G[k*H + d];

#define BRED(slot, expr) { float _v = (expr); \
    _v += __shfl_down_sync(0xffffffffu, _v, 16); \
    _v += __shfl_down_sync(0xffffffffu, _v, 8);  \
    _v += __shfl_down_sync(0xffffffffu, _v, 4);  \
    _v += __shfl_down_sync(0xffffffffu, _v, 2);  \
    _v += __shfl_down_sync(0xffffffffu, _v, 1);  \
    if (lane == 0) atomicAdd(&s[slot], _v); }

#pragma unroll
    for (int k = 0; k < NT; k++) BRED(k, g[k]);
    {
        int idx = NT;
#pragma unroll
        for (int k = 0; k < NT; k++)
#pragma unroll
            for (int l = k; l < NT; l++) { BRED(idx, g[k]*g[l]); idx++; }
    }
    __syncthreads();
    if (d == 0) {
        for (int k = 0; k < NT; k++) g_SG[k] = s[k];
        float q[QN];
        for (int m = 0; m < QN; m++) q[m] = 0.0f;
        int idx = NT;
        for (int k = 0; k < NT; k++)
            for (int l = k; l < NT; l++) {
                q[k+l] += (k == l ? 1.0f : 2.0f) * s[idx];
                idx++;
            }
        for (int m = 0; m < QN; m++) g_Q[m] = q[m];
    }
}

// ---------------- kernel 1d: per-emb-row Se, Se2, D_k (warp x 4 rows) ------------
// R7-proven configuration: 4 rows/warp = 24 independent LDG.128 in flight.
__global__ void __launch_bounds__(256, 3) emb_stats_kernel(const float* __restrict__ emb) {
    __shared__ float4 sG[NT * 192];         // 24 KB
    int tid  = threadIdx.x;
    int lane = tid & 31, warp = tid >> 5;   // 8 warps
    const float4* G4 = (const float4*)g_G;
    for (int i = tid; i < NT * 192; i += 256) sG[i] = G4[i];
    __syncthreads();

    int r0 = (blockIdx.x * 8 + warp) * 4;
    if (r0 > NF) return;
    int nrow = NF + 1 - r0; if (nrow > 4) nrow = 4;

    const float4* emb4 = (const float4*)emb;
    float acc[4][NT+2];
#pragma unroll
    for (int t = 0; t < 4; t++)
#pragma unroll
        for (int i = 0; i < NT+2; i++) acc[t][i] = 0.0f;

#pragma unroll
    for (int j = 0; j < 6; j++) {
        int dg = lane + 32*j;
        float4 e[4];
#pragma unroll
        for (int t = 0; t < 4; t++)
            e[t] = (t < nrow) ? __ldg(&emb4[(size_t)(r0 + t) * 192 + dg])
                              : make_float4(0.f, 0.f, 0.f, 0.f);
#pragma unroll
        for (int t = 0; t < 4; t++) {
            acc[t][0] += e[t].x + e[t].y + e[t].z + e[t].w;
            acc[t][1] += e[t].x*e[t].x + e[t].y*e[t].y + e[t].z*e[t].z + e[t].w*e[t].w;
        }
#pragma unroll
        for (int k = 0; k < NT; k++) {
            float4 g = sG[k*192 + dg];
#pragma unroll
            for (int t = 0; t < 4; t++)
                acc[t][2+k] += e[t].x*g.x + e[t].y*g.y + e[t].z*g.z + e[t].w*g.w;
        }
    }
#pragma unroll
    for (int t = 0; t < 4; t++)
#pragma unroll
        for (int i = 0; i < NT+2; i++) {
            float v = acc[t][i];
            v += __shfl_down_sync(0xffffffffu, v, 16);
            v += __shfl_down_sync(0xffffffffu, v, 8);
            v += __shfl_down_sync(0xffffffffu, v, 4);
            v += __shfl_down_sync(0xffffffffu, v, 2);
            v += __shfl_down_sync(0xffffffffu, v, 1);
            acc[t][i] = v;
        }
    if (lane == 0) {
        for (int t = 0; t < nrow; t++) {
            int r = r0 + t;
            g_Se[r]  = acc[t][0];
            g_Se2[r] = acc[t][1];
            float4* D4 = (float4*)&g_D[r * NT];
            D4[0] = make_float4(acc[t][2], acc[t][3], acc[t][4], acc[t][5]);
            D4[1] = make_float4(acc[t][6], acc[t][7], acc[t][8], acc[t][9]);
        }
    }
}

// ---------------- kernel 2: top-512 + fused closed-form LN stats -----------------
#define TK_T 512
#define TK_R 20      // 512*20 = 10240 >= NF
__global__ void __launch_bounds__(TK_T, 2) topk_kernel(const float* __restrict__ x,
                                                       float* __restrict__ out,
                                                       int write_mask) {
    __shared__ float xrow[NF];
    __shared__ unsigned long long cand[K];
    __shared__ int wsum[16];
    __shared__ int s_ge;
    __shared__ int scnt;

    int b    = blockIdx.x;
    int tid  = threadIdx.x;
    int lane = tid & 31, warp = tid >> 5;
    const float4* xr4 = (const float4*)(x + (size_t)b * NF);
    for (int i = tid; i < NF/4; i += TK_T) ((float4*)xrow)[i] = xr4[i];
    if (tid == 0) scnt = 0;
    __syncthreads();

    unsigned long long keys[TK_R];
#pragma unroll
    for (int r = 0; r < TK_R; r++) {
        int i = tid + r * TK_T;
        unsigned long long kb = 0ull;
        if (i < NF) {
            unsigned int ab = __float_as_uint(fabsf(xrow[i]));
            kb = ((unsigned long long)ab << 32) | (unsigned int)(~i);
        }
        keys[r] = kb;
    }

#define COUNT_GE(trial, res) { \
    int _c = 0; \
    _Pragma("unroll") \
    for (int _r = 0; _r < TK_R; _r++) _c += (keys[_r] >= (trial)) ? 1 : 0; \
    _c = __reduce_add_sync(0xffffffffu, _c); \
    if (lane == 0) wsum[warp] = _c; \
    __syncthreads(); \
    if (warp == 0) { \
        int _t = (lane < 16) ? wsum[lane] : 0; \
        _t = __reduce_add_sync(0xffffffffu, _t); \
        if (lane == 0) s_ge = _t; \
    } \
    __syncthreads(); \
    res = s_ge; }

    unsigned long long prefix = 0ull;
    int cbest = TK_T * TK_R;
    for (int bit = 62; bit >= 32; bit--) {
        unsigned long long trial = prefix | (1ull << bit);
        int c; COUNT_GE(trial, c);
        if (c >= K) { prefix = trial; cbest = c; }
    }
    if (cbest != K) {
        prefix |= 0xFFFFC000ull;            // constant bits 31..14 of every real key
        for (int bit = 13; bit >= 0; bit--) {
            unsigned long long trial = prefix | (1ull << bit);
            int c; COUNT_GE(trial, c);
            if (c >= K) prefix = trial;
        }
    }

#pragma unroll
    for (int r = 0; r < TK_R; r++) {
        if (keys[r] >= prefix) {
            int p = atomicAdd(&scnt, 1);
            if (p < K) cand[p] = keys[r];
        }
    }
    __syncthreads();

    // bitonic sort 512, descending
    for (int sz = 2; sz <= K; sz <<= 1) {
        for (int j = sz >> 1; j > 0; j >>= 1) {
            int ixj = tid ^ j;
            if (ixj > tid) {
                unsigned long long av = cand[tid], bv = cand[ixj];
                bool desc = ((tid & sz) == 0);
                if (desc ? (av < bv) : (av > bv)) { cand[tid] = bv; cand[ixj] = av; }
            }
            __syncthreads();
        }
    }

    unsigned long long key = cand[tid];
    unsigned int hi  = (unsigned int)(key >> 32);
    unsigned int idx = ~(unsigned int)key;
    int   active = (hi != 0u) ? 1 : 0;
    float v   = active ? xrow[idx] : 0.0f;
    int   fid = active ? (int)idx + 1 : 0;

    int nact  = __syncthreads_count(active);
    int empty = (nact == 0) ? 1 : 0;

    // ---- fused closed-form LN stats for this token ----
    float ps = g_SG[NT-1];
#pragma unroll
    for (int k = NT-2; k >= 0; k--) ps = fmaf(ps, v, g_SG[k]);
    float sumh = g_Se[fid] + ps;

    const float4* D4 = (const float4*)&g_D[fid * NT];
    float4 d0 = D4[0], d1 = D4[1];
    float D[NT] = {d0.x, d0.y, d0.z, d0.w, d1.x, d1.y, d1.z, d1.w};
    float pd = D[NT-1];
#pragma unroll
    for (int k = NT-2; k >= 0; k--) pd = fmaf(pd, v, D[k]);
    float pq = g_Q[QN-1];
#pragma unroll
    for (int m = QN-2; m >= 0; m--) pq = fmaf(pq, v, g_Q[m]);
    float sumh2 = g_Se2[fid] + 2.0f*pd + pq;

    float mu   = sumh * (1.0f / H);
    float var  = sumh2 * (1.0f / H) - mu * mu;
    float rstd = rsqrtf(var + 1e-5f);

    unsigned int enc = (unsigned int)fid;
    if (tid == 0 && empty) enc |= 0x80000000u;
    g_tok[b*K + tid] = make_float4(v, __uint_as_float(enc), mu, rstd);

    if (write_mask) {
        float m = (float)active;
        if (tid == 0 && empty) m = 1.0f;
        out[(size_t)TOK * H + (size_t)b * K + tid] = m;
    }
}

// ---------------- kernel 3: fused gather + poly + LN (f32x2 packed math) ---------
#define FU_TPB 64
__global__ void __launch_bounds__(192, 5) fuse_kernel(const float* __restrict__ emb,
                                                      const float* __restrict__ lnw,
                                                      const float* __restrict__ lnb,
                                                      float* __restrict__ out) {
    int dg = threadIdx.x;                   // 0..191 -> dims 4*dg..4*dg+3
    u64 Gxy[NT], Gzw[NT];
#pragma unroll
    for (int k = 0; k < NT; k++) {
        float4 g = ((const float4*)g_G)[k*192 + dg];
        Gxy[k] = pk2(g.x, g.y);
        Gzw[k] = pk2(g.z, g.w);
    }
    float4 lwf = ((const float4*)lnw)[dg];
    float4 lbf = ((const float4*)lnb)[dg];
    u64 lwxy = pk2(lwf.x, lwf.y), lwzw = pk2(lwf.z, lwf.w);
    u64 lbxy = pk2(lbf.x, lbf.y), lbzw = pk2(lbf.z, lbf.w);
    const float4* emb4 = (const float4*)emb;
    float4* out4 = (float4*)out;

    int t0 = blockIdx.x * FU_TPB;
    for (int tt = t0; tt < t0 + FU_TPB; tt += 4) {
#pragma unroll
        for (int j = 0; j < 4; j++) {
            int tok = tt + j;
            float4 t = g_tok[tok];
            int enc = __float_as_int(t.y);
            float4 e = __ldg(&emb4[(size_t)(enc & 0x7fffffff) * 192 + dg]);
            float v = t.x, mu = t.z, rstd = t.w;

            u64 vv = pk2(v, v);
            u64 rr = pk2(rstd, rstd);
            float nmr = -mu * rstd;
            u64 mm = pk2(nmr, nmr);

            u64 pxy = Gxy[NT-1], pzw = Gzw[NT-1];
#pragma unroll
            for (int k = NT-2; k >= 0; k--) {
                pxy = fma2(pxy, vv, Gxy[k]);
                pzw = fma2(pzw, vv, Gzw[k]);
            }
            u64 hxy = add2(pk2(e.x, e.y), pxy);
            u64 hzw = add2(pk2(e.z, e.w), pzw);
            u64 txy = fma2(hxy, rr, mm);
            u64 tzw = fma2(hzw, rr, mm);
            u64 oxy = fma2(txy, lwxy, lbxy);
            u64 ozw = fma2(tzw, lwzw, lbzw);

            float4 o;
            upk2(oxy, o.x, o.y);
            upk2(ozw, o.z, o.w);
            if (enc < 0) { o.x = 0.0f; o.y = 0.0f; o.z = 0.0f; o.w = 0.0f; }
            __stcs(&out4[(size_t)tok * 192 + dg], o);
        }
    }
}

// ---------------- launch --------------------------------------------------------
extern "C" void kernel_launch(void* const* d_in, const int* in_sizes, int n_in,
                              void* d_out, int out_size) {
    const float* x   = (const float*)d_in[0];
    const float* emb = (const float*)d_in[1];
    const float* w1  = (const float*)d_in[2];
    const float* b1  = (const float*)d_in[3];
    const float* w2  = (const float*)d_in[4];
    const float* b2  = (const float*)d_in[5];
    const float* lnw = (const float*)d_in[6];
    const float* lnb = (const float*)d_in[7];
    float* out = (float*)d_out;

    int write_mask = (out_size >= TOK * H + TOK) ? 1 : 0;

    zero_G_kernel<<<6, 1024>>>();
    gvec_kernel<<<dim3(H/128, GV_HB), 128>>>(w1, b1, w2, b2);
    poly_stats_kernel<<<1, H>>>();
    emb_stats_kernel<<<313, 256>>>(emb);
    topk_kernel<<<B, TK_T>>>(x, out, write_mask);
    fuse_kernel<<<TOK/FU_TPB, 192>>>(emb, lnw, lnb, out);
}

// round 13
// speedup vs baseline: 1.7898x; 1.0190x over previous
#include <cuda_runtime.h>
#include <math.h>

#define B   256
#define NF  10000
#define H   768
#define K   512
#define NT  6
#define QN  (2*NT-1)
#define TOK (B*K)

typedef unsigned long long u64;
__device__ __forceinline__ u64 pk2(float lo, float hi) {
    u64 r; asm("mov.b64 %0, {%1, %2};" : "=l"(r) : "f"(lo), "f"(hi)); return r;
}
__device__ __forceinline__ void upk2(u64 v, float& lo, float& hi) {
    asm("mov.b64 {%0, %1}, %2;" : "=f"(lo), "=f"(hi) : "l"(v));
}
__device__ __forceinline__ u64 fma2(u64 a, u64 b, u64 c) {
    u64 d; asm("fma.rn.f32x2 %0, %1, %2, %3;" : "=l"(d) : "l"(a), "l"(b), "l"(c)); return d;
}
__device__ __forceinline__ u64 add2(u64 a, u64 b) {
    u64 d; asm("add.rn.f32x2 %0, %1, %2;" : "=l"(d) : "l"(a), "l"(b)); return d;
}

// ---------------- scratch ----------------
__device__ __align__(16) float g_G[NT*H];
__device__ float g_SG[NT];
__device__ float g_Q[QN];
__device__ float g_Se[NF+1];
__device__ float g_Se2[NF+1];
__device__ __align__(16) float g_D[(NF+1)*8];   // 6 used + 2 pad for float4 alignment
__device__ float4 g_tok[TOK];

// ---------------- kernel 0: zero g_G for gvec atomics ---------------------------
__global__ void zero_G_kernel() {
    int i = blockIdx.x * 1024 + threadIdx.x;
    if (i < NT*H) g_G[i] = 0.0f;
}

// ---------------- kernel 1: G_k = w2^T c_k (+ b2 into k=0) ----------------------
#define GV_HB 32
#define GV_HC (H / GV_HB)
__global__ void gvec_kernel(const float* __restrict__ w1, const float* __restrict__ b1,
                            const float* __restrict__ w2, const float* __restrict__ b2) {
    __shared__ float sc[NT * GV_HC];
    int tid = threadIdx.x;                  // 128
    int d   = blockIdx.x * 128 + tid;
    int h0  = blockIdx.y * GV_HC;

    if (tid < GV_HC) {
        int h = h0 + tid;
        float a    = w1[h];
        float beta = b1[h];
        float phi = 0.3989422804f * expf(-0.5f * beta * beta);
        float Phi = 0.5f * (1.0f + erff(beta * 0.7071067812f));
        sc[0*GV_HC + tid] = beta * Phi;                 // gelu(beta)
        sc[1*GV_HC + tid] = (Phi + beta * phi) * a;     // gelu'(beta)*a
        float He_km2 = 1.0f, He_km1 = beta, fact = 1.0f, apow = a;
#pragma unroll
        for (int k = 2; k < NT; k++) {
            fact *= (float)k;
            apow *= a;
            float s  = (k & 1) ? -1.0f : 1.0f;
            float gk = phi * s * ((float)k * He_km2 - beta * He_km1);
            sc[k*GV_HC + tid] = gk * apow / fact;
            float He_k = beta * He_km1 - (float)(k - 1) * He_km2;
            He_km2 = He_km1; He_km1 = He_k;
        }
    }
    __syncthreads();

    float acc[NT];
#pragma unroll
    for (int k = 0; k < NT; k++) acc[k] = 0.0f;
#pragma unroll 4
    for (int h = 0; h < GV_HC; h++) {
        float w = w2[(size_t)(h0 + h) * H + d];
#pragma unroll
        for (int k = 0; k < NT; k++) acc[k] = fmaf(sc[k*GV_HC + h], w, acc[k]);
    }
    if (blockIdx.y == 0) acc[0] += b2[d];
#pragma unroll
    for (int k = 0; k < NT; k++) atomicAdd(&g_G[k*H + d], acc[k]);
}

// ---------------- kernel 1c: SG_k and Q_m (1 block, 768 threads) -----------------
__global__ void poly_stats_kernel() {
    __shared__ float s[NT + NT*(NT+1)/2];
    int d = threadIdx.x;
    int lane = d & 31;
    if (d < NT + NT*(NT+1)/2) s[d] = 0.0f;
    __syncthreads();
    float g[NT];
#pragma unroll
    for (int k = 0; k < NT; k++) g[k] = g_G[k*H + d];

#define BRED(slot, expr) { float _v = (expr); \
    _v += __shfl_down_sync(0xffffffffu, _v, 16); \
    _v += __shfl_down_sync(0xffffffffu, _v, 8);  \
    _v += __shfl_down_sync(0xffffffffu, _v, 4);  \
    _v += __shfl_down_sync(0xffffffffu, _v, 2);  \
    _v += __shfl_down_sync(0xffffffffu, _v, 1);  \
    if (lane == 0) atomicAdd(&s[slot], _v); }

#pragma unroll
    for (int k = 0; k < NT; k++) BRED(k, g[k]);
    {
        int idx = NT;
#pragma unroll
        for (int k = 0; k < NT; k++)
#pragma unroll
            for (int l = k; l < NT; l++) { BRED(idx, g[k]*g[l]); idx++; }
    }
    __syncthreads();
    if (d == 0) {
        for (int k = 0; k < NT; k++) g_SG[k] = s[k];
        float q[QN];
        for (int m = 0; m < QN; m++) q[m] = 0.0f;
        int idx = NT;
        for (int k = 0; k < NT; k++)
            for (int l = k; l < NT; l++) {
                q[k+l] += (k == l ? 1.0f : 2.0f) * s[idx];
                idx++;
            }
        for (int m = 0; m < QN; m++) g_Q[m] = q[m];
    }
}

// ---------------- kernel 1d: per-emb-row Se, Se2, D_k (warp x 4 rows) ------------
// R7-proven configuration: 4 rows/warp = 24 independent LDG.128 in flight.
__global__ void __launch_bounds__(256, 3) emb_stats_kernel(const float* __restrict__ emb) {
    __shared__ float4 sG[NT * 192];         // 18 KB
    int tid  = threadIdx.x;
    int lane = tid & 31, warp = tid >> 5;   // 8 warps
    const float4* G4 = (const float4*)g_G;
    for (int i = tid; i < NT * 192; i += 256) sG[i] = G4[i];
    __syncthreads();

    int r0 = (blockIdx.x * 8 + warp) * 4;
    if (r0 > NF) return;
    int nrow = NF + 1 - r0; if (nrow > 4) nrow = 4;

    const float4* emb4 = (const float4*)emb;
    float acc[4][NT+2];
#pragma unroll
    for (int t = 0; t < 4; t++)
#pragma unroll
        for (int i = 0; i < NT+2; i++) acc[t][i] = 0.0f;

#pragma unroll
    for (int j = 0; j < 6; j++) {
        int dg = lane + 32*j;
        float4 e[4];
#pragma unroll
        for (int t = 0; t < 4; t++)
            e[t] = (t < nrow) ? __ldg(&emb4[(size_t)(r0 + t) * 192 + dg])
                              : make_float4(0.f, 0.f, 0.f, 0.f);
#pragma unroll
        for (int t = 0; t < 4; t++) {
            acc[t][0] += e[t].x + e[t].y + e[t].z + e[t].w;
            acc[t][1] += e[t].x*e[t].x + e[t].y*e[t].y + e[t].z*e[t].z + e[t].w*e[t].w;
        }
#pragma unroll
        for (int k = 0; k < NT; k++) {
            float4 g = sG[k*192 + dg];
#pragma unroll
            for (int t = 0; t < 4; t++)
                acc[t][2+k] += e[t].x*g.x + e[t].y*g.y + e[t].z*g.z + e[t].w*g.w;
        }
    }
#pragma unroll
    for (int t = 0; t < 4; t++)
#pragma unroll
        for (int i = 0; i < NT+2; i++) {
            float v = acc[t][i];
            v += __shfl_down_sync(0xffffffffu, v, 16);
            v += __shfl_down_sync(0xffffffffu, v, 8);
            v += __shfl_down_sync(0xffffffffu, v, 4);
            v += __shfl_down_sync(0xffffffffu, v, 2);
            v += __shfl_down_sync(0xffffffffu, v, 1);
            acc[t][i] = v;
        }
    if (lane == 0) {
        for (int t = 0; t < nrow; t++) {
            int r = r0 + t;
            g_Se[r]  = acc[t][0];
            g_Se2[r] = acc[t][1];
            float4* D4 = (float4*)&g_D[r * 8];
            D4[0] = make_float4(acc[t][2], acc[t][3], acc[t][4], acc[t][5]);
            D4[1] = make_float4(acc[t][6], acc[t][7], 0.0f, 0.0f);
        }
    }
}

// ---------------- kernel 2: top-512 + fused closed-form LN stats -----------------
#define TK_T 512
#define TK_R 20      // 512*20 = 10240 >= NF
__global__ void __launch_bounds__(TK_T, 2) topk_kernel(const float* __restrict__ x,
                                                       float* __restrict__ out,
                                                       int write_mask) {
    __shared__ float xrow[NF];
    __shared__ unsigned long long cand[K];
    __shared__ int wsum[16];
    __shared__ int s_ge;
    __shared__ int scnt;

    int b    = blockIdx.x;
    int tid  = threadIdx.x;
    int lane = tid & 31, warp = tid >> 5;
    const float4* xr4 = (const float4*)(x + (size_t)b * NF);
    for (int i = tid; i < NF/4; i += TK_T) ((float4*)xrow)[i] = xr4[i];
    if (tid == 0) scnt = 0;
    __syncthreads();

    unsigned long long keys[TK_R];
#pragma unroll
    for (int r = 0; r < TK_R; r++) {
        int i = tid + r * TK_T;
        unsigned long long kb = 0ull;
        if (i < NF) {
            unsigned int ab = __float_as_uint(fabsf(xrow[i]));
            kb = ((unsigned long long)ab << 32) | (unsigned int)(~i);
        }
        keys[r] = kb;
    }

#define COUNT_GE(trial, res) { \
    int _c = 0; \
    _Pragma("unroll") \
    for (int _r = 0; _r < TK_R; _r++) _c += (keys[_r] >= (trial)) ? 1 : 0; \
    _c = __reduce_add_sync(0xffffffffu, _c); \
    if (lane == 0) wsum[warp] = _c; \
    __syncthreads(); \
    if (warp == 0) { \
        int _t = (lane < 16) ? wsum[lane] : 0; \
        _t = __reduce_add_sync(0xffffffffu, _t); \
        if (lane == 0) s_ge = _t; \
    } \
    __syncthreads(); \
    res = s_ge; }

    unsigned long long prefix = 0ull;
    int cbest = TK_T * TK_R;
    for (int bit = 62; bit >= 32; bit--) {
        unsigned long long trial = prefix | (1ull << bit);
        int c; COUNT_GE(trial, c);
        if (c >= K) { prefix = trial; cbest = c; }
    }
    if (cbest != K) {
        prefix |= 0xFFFFC000ull;            // constant bits 31..14 of every real key
        for (int bit = 13; bit >= 0; bit--) {
            unsigned long long trial = prefix | (1ull << bit);
            int c; COUNT_GE(trial, c);
            if (c >= K) prefix = trial;
        }
    }

#pragma unroll
    for (int r = 0; r < TK_R; r++) {
        if (keys[r] >= prefix) {
            int p = atomicAdd(&scnt, 1);
            if (p < K) cand[p] = keys[r];
        }
    }
    __syncthreads();

    // bitonic sort 512, descending
    for (int sz = 2; sz <= K; sz <<= 1) {
        for (int j = sz >> 1; j > 0; j >>= 1) {
            int ixj = tid ^ j;
            if (ixj > tid) {
                unsigned long long av = cand[tid], bv = cand[ixj];
                bool desc = ((tid & sz) == 0);
                if (desc ? (av < bv) : (av > bv)) { cand[tid] = bv; cand[ixj] = av; }
            }
            __syncthreads();
        }
    }

    unsigned long long key = cand[tid];
    unsigned int hi  = (unsigned int)(key >> 32);
    unsigned int idx = ~(unsigned int)key;
    int   active = (hi != 0u) ? 1 : 0;
    float v   = active ? xrow[idx] : 0.0f;
    int   fid = active ? (int)idx + 1 : 0;

    int nact  = __syncthreads_count(active);
    int empty = (nact == 0) ? 1 : 0;

    // ---- fused closed-form LN stats for this token ----
    float ps = g_SG[NT-1];
#pragma unroll
    for (int k = NT-2; k >= 0; k--) ps = fmaf(ps, v, g_SG[k]);
    float sumh = g_Se[fid] + ps;

    const float4* D4 = (const float4*)&g_D[fid * 8];
    float4 d0 = D4[0], d1 = D4[1];
    float D[NT] = {d0.x, d0.y, d0.z, d0.w, d1.x, d1.y};
    float pd = D[NT-1];
#pragma unroll
    for (int k = NT-2; k >= 0; k--) pd = fmaf(pd, v, D[k]);
    float pq = g_Q[QN-1];
#pragma unroll
    for (int m = QN-2; m >= 0; m--) pq = fmaf(pq, v, g_Q[m]);
    float sumh2 = g_Se2[fid] + 2.0f*pd + pq;

    float mu   = sumh * (1.0f / H);
    float var  = sumh2 * (1.0f / H) - mu * mu;
    float rstd = rsqrtf(var + 1e-5f);

    unsigned int enc = (unsigned int)fid;
    if (tid == 0 && empty) enc |= 0x80000000u;
    g_tok[b*K + tid] = make_float4(v, __uint_as_float(enc), mu, rstd);

    if (write_mask) {
        float m = (float)active;
        if (tid == 0 && empty) m = 1.0f;
        out[(size_t)TOK * H + (size_t)b * K + tid] = m;
    }
}

// ---------------- kernel 3: fused gather + poly + LN (f32x2 packed math) ---------
#define FU_TPB 64
__global__ void __launch_bounds__(192, 5) fuse_kernel(const float* __restrict__ emb,
                                                      const float* __restrict__ lnw,
                                                      const float* __restrict__ lnb,
                                                      float* __restrict__ out) {
    int dg = threadIdx.x;                   // 0..191 -> dims 4*dg..4*dg+3
    u64 Gxy[NT], Gzw[NT];
#pragma unroll
    for (int k = 0; k < NT; k++) {
        float4 g = ((const float4*)g_G)[k*192 + dg];
        Gxy[k] = pk2(g.x, g.y);
        Gzw[k] = pk2(g.z, g.w);
    }
    float4 lwf = ((const float4*)lnw)[dg];
    float4 lbf = ((const float4*)lnb)[dg];
    u64 lwxy = pk2(lwf.x, lwf.y), lwzw = pk2(lwf.z, lwf.w);
    u64 lbxy = pk2(lbf.x, lbf.y), lbzw = pk2(lbf.z, lbf.w);
    const float4* emb4 = (const float4*)emb;
    float4* out4 = (float4*)out;

    int t0 = blockIdx.x * FU_TPB;
    for (int tt = t0; tt < t0 + FU_TPB; tt += 8) {
#pragma unroll
        for (int j = 0; j < 8; j++) {
            int tok = tt + j;
            float4 t = g_tok[tok];
            int enc = __float_as_int(t.y);
            float4 e = __ldg(&emb4[(size_t)(enc & 0x7fffffff) * 192 + dg]);
            float v = t.x, mu = t.z, rstd = t.w;

            u64 vv = pk2(v, v);
            u64 rr = pk2(rstd, rstd);
            float nmr = -mu * rstd;
            u64 mm = pk2(nmr, nmr);

            u64 pxy = Gxy[NT-1], pzw = Gzw[NT-1];
#pragma unroll
            for (int k = NT-2; k >= 0; k--) {
                pxy = fma2(pxy, vv, Gxy[k]);
                pzw = fma2(pzw, vv, Gzw[k]);
            }
            u64 hxy = add2(pk2(e.x, e.y), pxy);
            u64 hzw = add2(pk2(e.z, e.w), pzw);
            u64 txy = fma2(hxy, rr, mm);
            u64 tzw = fma2(hzw, rr, mm);
            u64 oxy = fma2(txy, lwxy, lbxy);
            u64 ozw = fma2(tzw, lwzw, lbzw);

            float4 o;
            upk2(oxy, o.x, o.y);
            upk2(ozw, o.z, o.w);
            if (enc < 0) { o.x = 0.0f; o.y = 0.0f; o.z = 0.0f; o.w = 0.0f; }
            __stcs(&out4[(size_t)tok * 192 + dg], o);
        }
    }
}

// ---------------- launch --------------------------------------------------------
extern "C" void kernel_launch(void* const* d_in, const int* in_sizes, int n_in,
                              void* d_out, int out_size) {
    const float* x   = (const float*)d_in[0];
    const float* emb = (const float*)d_in[1];
    const float* w1  = (const float*)d_in[2];
    const float* b1  = (const float*)d_in[3];
    const float* w2  = (const float*)d_in[4];
    const float* b2  = (const float*)d_in[5];
    const float* lnw = (const float*)d_in[6];
    const float* lnb = (const float*)d_in[7];
    float* out = (float*)d_out;

    int write_mask = (out_size >= TOK * H + TOK) ? 1 : 0;

    zero_G_kernel<<<5, 1024>>>();
    gvec_kernel<<<dim3(H/128, GV_HB), 128>>>(w1, b1, w2, b2);
    poly_stats_kernel<<<1, H>>>();
    emb_stats_kernel<<<313, 256>>>(emb);
    topk_kernel<<<B, TK_T>>>(x, out, write_mask);
    fuse_kernel<<<TOK/FU_TPB, 192>>>(emb, lnw, lnb, out);
}

// round 14
// speedup vs baseline: 2.0000x; 1.1174x over previous
#include <cuda_runtime.h>
#include <math.h>

#define B   256
#define NF  10000
#define H   768
#define K   512
#define NT  6
#define QN  (2*NT-1)
#define TOK (B*K)

typedef unsigned long long u64;
__device__ __forceinline__ u64 pk2(float lo, float hi) {
    u64 r; asm("mov.b64 %0, {%1, %2};" : "=l"(r) : "f"(lo), "f"(hi)); return r;
}
__device__ __forceinline__ void upk2(u64 v, float& lo, float& hi) {
    asm("mov.b64 {%0, %1}, %2;" : "=f"(lo), "=f"(hi) : "l"(v));
}
__device__ __forceinline__ u64 fma2(u64 a, u64 b, u64 c) {
    u64 d; asm("fma.rn.f32x2 %0, %1, %2, %3;" : "=l"(d) : "l"(a), "l"(b), "l"(c)); return d;
}
__device__ __forceinline__ u64 add2(u64 a, u64 b) {
    u64 d; asm("add.rn.f32x2 %0, %1, %2;" : "=l"(d) : "l"(a), "l"(b)); return d;
}

// ---------------- scratch ----------------
__device__ __align__(16) float g_G[NT*H];
__device__ float g_SG[NT];
__device__ float g_Q[QN];
__device__ float g_Se[NF+1];
__device__ float g_Se2[NF+1];
__device__ __align__(16) float g_D[(NF+1)*8];   // 6 used + 2 pad for float4 alignment
__device__ float g_vals[TOK];
__device__ int   g_fid[TOK];
__device__ int   g_empty[B];
__device__ float4 g_tok[TOK];

// ---------------- kernel 0: zero g_G for gvec atomics ---------------------------
__global__ void zero_G_kernel() {
    int i = blockIdx.x * 1024 + threadIdx.x;
    if (i < NT*H) g_G[i] = 0.0f;
}

// ---------------- kernel 1: G_k = w2^T c_k (+ b2 into k=0) ----------------------
#define GV_HB 32
#define GV_HC (H / GV_HB)
__global__ void gvec_kernel(const float* __restrict__ w1, const float* __restrict__ b1,
                            const float* __restrict__ w2, const float* __restrict__ b2) {
    __shared__ float sc[NT * GV_HC];
    int tid = threadIdx.x;                  // 128
    int d   = blockIdx.x * 128 + tid;
    int h0  = blockIdx.y * GV_HC;

    if (tid < GV_HC) {
        int h = h0 + tid;
        float a    = w1[h];
        float beta = b1[h];
        float phi = 0.3989422804f * expf(-0.5f * beta * beta);
        float Phi = 0.5f * (1.0f + erff(beta * 0.7071067812f));
        sc[0*GV_HC + tid] = beta * Phi;                 // gelu(beta)
        sc[1*GV_HC + tid] = (Phi + beta * phi) * a;     // gelu'(beta)*a
        float He_km2 = 1.0f, He_km1 = beta, fact = 1.0f, apow = a;
#pragma unroll
        for (int k = 2; k < NT; k++) {
            fact *= (float)k;
            apow *= a;
            float s  = (k & 1) ? -1.0f : 1.0f;
            float gk = phi * s * ((float)k * He_km2 - beta * He_km1);
            sc[k*GV_HC + tid] = gk * apow / fact;
            float He_k = beta * He_km1 - (float)(k - 1) * He_km2;
            He_km2 = He_km1; He_km1 = He_k;
        }
    }
    __syncthreads();

    float acc[NT];
#pragma unroll
    for (int k = 0; k < NT; k++) acc[k] = 0.0f;
#pragma unroll 4
    for (int h = 0; h < GV_HC; h++) {
        float w = w2[(size_t)(h0 + h) * H + d];
#pragma unroll
        for (int k = 0; k < NT; k++) acc[k] = fmaf(sc[k*GV_HC + h], w, acc[k]);
    }
    if (blockIdx.y == 0) acc[0] += b2[d];
#pragma unroll
    for (int k = 0; k < NT; k++) atomicAdd(&g_G[k*H + d], acc[k]);
}

// ---------------- kernel 1c: SG_k and Q_m (1 block, 768 threads) -----------------
__global__ void poly_stats_kernel() {
    __shared__ float s[NT + NT*(NT+1)/2];
    int d = threadIdx.x;
    int lane = d & 31;
    if (d < NT + NT*(NT+1)/2) s[d] = 0.0f;
    __syncthreads();
    float g[NT];
#pragma unroll
    for (int k = 0; k < NT; k++) g[k] = g_G[k*H + d];

#define BRED(slot, expr) { float _v = (expr); \
    _v += __shfl_down_sync(0xffffffffu, _v, 16); \
    _v += __shfl_down_sync(0xffffffffu, _v, 8);  \
    _v += __shfl_down_sync(0xffffffffu, _v, 4);  \
    _v += __shfl_down_sync(0xffffffffu, _v, 2);  \
    _v += __shfl_down_sync(0xffffffffu, _v, 1);  \
    if (lane == 0) atomicAdd(&s[slot], _v); }

#pragma unroll
    for (int k = 0; k < NT; k++) BRED(k, g[k]);
    {
        int idx = NT;
#pragma unroll
        for (int k = 0; k < NT; k++)
#pragma unroll
            for (int l = k; l < NT; l++) { BRED(idx, g[k]*g[l]); idx++; }
    }
    __syncthreads();
    if (d == 0) {
        for (int k = 0; k < NT; k++) g_SG[k] = s[k];
        float q[QN];
        for (int m = 0; m < QN; m++) q[m] = 0.0f;
        int idx = NT;
        for (int k = 0; k < NT; k++)
            for (int l = k; l < NT; l++) {
                q[k+l] += (k == l ? 1.0f : 2.0f) * s[idx];
                idx++;
            }
        for (int m = 0; m < QN; m++) g_Q[m] = q[m];
    }
}

// ---------------- kernel 1d: per-emb-row Se, Se2, D_k (warp x 4 rows) ------------
__global__ void __launch_bounds__(256, 3) emb_stats_kernel(const float* __restrict__ emb) {
    __shared__ float4 sG[NT * 192];         // 18 KB
    int tid  = threadIdx.x;
    int lane = tid & 31, warp = tid >> 5;   // 8 warps
    const float4* G4 = (const float4*)g_G;
    for (int i = tid; i < NT * 192; i += 256) sG[i] = G4[i];
    __syncthreads();

    int r0 = (blockIdx.x * 8 + warp) * 4;
    if (r0 > NF) return;
    int nrow = NF + 1 - r0; if (nrow > 4) nrow = 4;

    const float4* emb4 = (const float4*)emb;
    float acc[4][NT+2];
#pragma unroll
    for (int t = 0; t < 4; t++)
#pragma unroll
        for (int i = 0; i < NT+2; i++) acc[t][i] = 0.0f;

#pragma unroll
    for (int j = 0; j < 6; j++) {
        int dg = lane + 32*j;
        float4 e[4];
#pragma unroll
        for (int t = 0; t < 4; t++)
            e[t] = (t < nrow) ? __ldg(&emb4[(size_t)(r0 + t) * 192 + dg])
                              : make_float4(0.f, 0.f, 0.f, 0.f);
#pragma unroll
        for (int t = 0; t < 4; t++) {
            acc[t][0] += e[t].x + e[t].y + e[t].z + e[t].w;
            acc[t][1] += e[t].x*e[t].x + e[t].y*e[t].y + e[t].z*e[t].z + e[t].w*e[t].w;
        }
#pragma unroll
        for (int k = 0; k < NT; k++) {
            float4 g = sG[k*192 + dg];
#pragma unroll
            for (int t = 0; t < 4; t++)
                acc[t][2+k] += e[t].x*g.x + e[t].y*g.y + e[t].z*g.z + e[t].w*g.w;
        }
    }
#pragma unroll
    for (int t = 0; t < 4; t++)
#pragma unroll
        for (int i = 0; i < NT+2; i++) {
            float v = acc[t][i];
            v += __shfl_down_sync(0xffffffffu, v, 16);
            v += __shfl_down_sync(0xffffffffu, v, 8);
            v += __shfl_down_sync(0xffffffffu, v, 4);
            v += __shfl_down_sync(0xffffffffu, v, 2);
            v += __shfl_down_sync(0xffffffffu, v, 1);
            acc[t][i] = v;
        }
    if (lane == 0) {
        for (int t = 0; t < nrow; t++) {
            int r = r0 + t;
            g_Se[r]  = acc[t][0];
            g_Se2[r] = acc[t][1];
            float4* D4 = (float4*)&g_D[r * 8];
            D4[0] = make_float4(acc[t][2], acc[t][3], acc[t][4], acc[t][5]);
            D4[1] = make_float4(acc[t][6], acc[t][7], 0.0f, 0.0f);
        }
    }
}

// ---------------- kernel 2: per-row top-512 (dependency-free: only reads x) ------
#define TK_T 512
#define TK_R 20      // 512*20 = 10240 >= NF
__global__ void __launch_bounds__(TK_T, 2) topk_kernel(const float* __restrict__ x,
                                                       float* __restrict__ out,
                                                       int write_mask) {
    __shared__ float xrow[NF];
    __shared__ unsigned long long cand[K];
    __shared__ int wsum[16];
    __shared__ int s_ge;
    __shared__ int scnt;

    int b    = blockIdx.x;
    int tid  = threadIdx.x;
    int lane = tid & 31, warp = tid >> 5;
    const float4* xr4 = (const float4*)(x + (size_t)b * NF);
    for (int i = tid; i < NF/4; i += TK_T) ((float4*)xrow)[i] = xr4[i];
    if (tid == 0) scnt = 0;
    __syncthreads();

    unsigned long long keys[TK_R];
#pragma unroll
    for (int r = 0; r < TK_R; r++) {
        int i = tid + r * TK_T;
        unsigned long long kb = 0ull;
        if (i < NF) {
            unsigned int ab = __float_as_uint(fabsf(xrow[i]));
            kb = ((unsigned long long)ab << 32) | (unsigned int)(~i);
        }
        keys[r] = kb;
    }

#define COUNT_GE(trial, res) { \
    int _c = 0; \
    _Pragma("unroll") \
    for (int _r = 0; _r < TK_R; _r++) _c += (keys[_r] >= (trial)) ? 1 : 0; \
    _c = __reduce_add_sync(0xffffffffu, _c); \
    if (lane == 0) wsum[warp] = _c; \
    __syncthreads(); \
    if (warp == 0) { \
        int _t = (lane < 16) ? wsum[lane] : 0; \
        _t = __reduce_add_sync(0xffffffffu, _t); \
        if (lane == 0) s_ge = _t; \
    } \
    __syncthreads(); \
    res = s_ge; }

    unsigned long long prefix = 0ull;
    int cbest = TK_T * TK_R;
    for (int bit = 62; bit >= 32; bit--) {
        unsigned long long trial = prefix | (1ull << bit);
        int c; COUNT_GE(trial, c);
        if (c >= K) { prefix = trial; cbest = c; }
    }
    if (cbest != K) {
        prefix |= 0xFFFFC000ull;            // constant bits 31..14 of every real key
        for (int bit = 13; bit >= 0; bit--) {
            unsigned long long trial = prefix | (1ull << bit);
            int c; COUNT_GE(trial, c);
            if (c >= K) prefix = trial;
        }
    }

#pragma unroll
    for (int r = 0; r < TK_R; r++) {
        if (keys[r] >= prefix) {
            int p = atomicAdd(&scnt, 1);
            if (p < K) cand[p] = keys[r];
        }
    }
    __syncthreads();

    // bitonic sort 512, descending
    for (int sz = 2; sz <= K; sz <<= 1) {
        for (int j = sz >> 1; j > 0; j >>= 1) {
            int ixj = tid ^ j;
            if (ixj > tid) {
                unsigned long long av = cand[tid], bv = cand[ixj];
                bool desc = ((tid & sz) == 0);
                if (desc ? (av < bv) : (av > bv)) { cand[tid] = bv; cand[ixj] = av; }
            }
            __syncthreads();
        }
    }

    unsigned long long key = cand[tid];
    unsigned int hi  = (unsigned int)(key >> 32);
    unsigned int idx = ~(unsigned int)key;
    int   active = (hi != 0u) ? 1 : 0;
    float v   = active ? xrow[idx] : 0.0f;
    int   fid = active ? (int)idx + 1 : 0;

    int nact  = __syncthreads_count(active);
    int empty = (nact == 0) ? 1 : 0;

    g_vals[b*K + tid] = v;
    g_fid [b*K + tid] = fid;
    if (tid == 0) g_empty[b] = empty;
    if (write_mask) {
        float m = (float)active;
        if (tid == 0 && empty) m = 1.0f;
        out[(size_t)TOK * H + (size_t)b * K + tid] = m;
    }
}

// ---------------- kernel 2b: closed-form per-token LN statistics -----------------
__global__ void token_stats_kernel() {
    int tok = blockIdx.x * 256 + threadIdx.x;
    float v   = g_vals[tok];
    int   fid = g_fid[tok];

    float ps = g_SG[NT-1];
#pragma unroll
    for (int k = NT-2; k >= 0; k--) ps = fmaf(ps, v, g_SG[k]);
    float sumh = g_Se[fid] + ps;

    const float4* D4 = (const float4*)&g_D[fid * 8];
    float4 d0 = D4[0], d1 = D4[1];
    float D[NT] = {d0.x, d0.y, d0.z, d0.w, d1.x, d1.y};
    float pd = D[NT-1];
#pragma unroll
    for (int k = NT-2; k >= 0; k--) pd = fmaf(pd, v, D[k]);
    float pq = g_Q[QN-1];
#pragma unroll
    for (int m = QN-2; m >= 0; m--) pq = fmaf(pq, v, g_Q[m]);
    float sumh2 = g_Se2[fid] + 2.0f*pd + pq;

    float mu   = sumh * (1.0f / H);
    float var  = sumh2 * (1.0f / H) - mu * mu;
    float rstd = rsqrtf(var + 1e-5f);

    unsigned int enc = (unsigned int)fid;
    if ((tok & (K-1)) == 0 && g_empty[tok >> 9]) enc |= 0x80000000u;
    g_tok[tok] = make_float4(v, __uint_as_float(enc), mu, rstd);
}

// ---------------- kernel 3: fused gather + poly + LN (f32x2 packed math) ---------
#define FU_TPB 64
__global__ void __launch_bounds__(192, 5) fuse_kernel(const float* __restrict__ emb,
                                                      const float* __restrict__ lnw,
                                                      const float* __restrict__ lnb,
                                                      float* __restrict__ out) {
    int dg = threadIdx.x;                   // 0..191 -> dims 4*dg..4*dg+3
    u64 Gxy[NT], Gzw[NT];
#pragma unroll
    for (int k = 0; k < NT; k++) {
        float4 g = ((const float4*)g_G)[k*192 + dg];
        Gxy[k] = pk2(g.x, g.y);
        Gzw[k] = pk2(g.z, g.w);
    }
    float4 lwf = ((const float4*)lnw)[dg];
    float4 lbf = ((const float4*)lnb)[dg];
    u64 lwxy = pk2(lwf.x, lwf.y), lwzw = pk2(lwf.z, lwf.w);
    u64 lbxy = pk2(lbf.x, lbf.y), lbzw = pk2(lbf.z, lbf.w);
    const float4* emb4 = (const float4*)emb;
    float4* out4 = (float4*)out;

    int t0 = blockIdx.x * FU_TPB;
    for (int tt = t0; tt < t0 + FU_TPB; tt += 8) {
#pragma unroll
        for (int j = 0; j < 8; j++) {
            int tok = tt + j;
            float4 t = g_tok[tok];
            int enc = __float_as_int(t.y);
            float4 e = __ldg(&emb4[(size_t)(enc & 0x7fffffff) * 192 + dg]);
            float v = t.x, mu = t.z, rstd = t.w;

            u64 vv = pk2(v, v);
            u64 rr = pk2(rstd, rstd);
            float nmr = -mu * rstd;
            u64 mm = pk2(nmr, nmr);

            u64 pxy = Gxy[NT-1], pzw = Gzw[NT-1];
#pragma unroll
            for (int k = NT-2; k >= 0; k--) {
                pxy = fma2(pxy, vv, Gxy[k]);
                pzw = fma2(pzw, vv, Gzw[k]);
            }
            u64 hxy = add2(pk2(e.x, e.y), pxy);
            u64 hzw = add2(pk2(e.z, e.w), pzw);
            u64 txy = fma2(hxy, rr, mm);
            u64 tzw = fma2(hzw, rr, mm);
            u64 oxy = fma2(txy, lwxy, lbxy);
            u64 ozw = fma2(tzw, lwzw, lbzw);

            float4 o;
            upk2(oxy, o.x, o.y);
            upk2(ozw, o.z, o.w);
            if (enc < 0) { o.x = 0.0f; o.y = 0.0f; o.z = 0.0f; o.w = 0.0f; }
            __stcs(&out4[(size_t)tok * 192 + dg], o);
        }
    }
}

// ---------------- launch --------------------------------------------------------
extern "C" void kernel_launch(void* const* d_in, const int* in_sizes, int n_in,
                              void* d_out, int out_size) {
    const float* x   = (const float*)d_in[0];
    const float* emb = (const float*)d_in[1];
    const float* w1  = (const float*)d_in[2];
    const float* b1  = (const float*)d_in[3];
    const float* w2  = (const float*)d_in[4];
    const float* b2  = (const float*)d_in[5];
    const float* lnw = (const float*)d_in[6];
    const float* lnb = (const float*)d_in[7];
    float* out = (float*)d_out;

    int write_mask = (out_size >= TOK * H + TOK) ? 1 : 0;

    // Lazy one-time creation of the side stream + fork/join events (host
    // resources, not device memory; same objects reused every call so the
    // captured work is identical on every invocation).
    static cudaStream_t s2 = nullptr;
    static cudaEvent_t evFork = nullptr, evJoin = nullptr;
    if (s2 == nullptr) {
        cudaStreamCreateWithFlags(&s2, cudaStreamNonBlocking);
        cudaEventCreateWithFlags(&evFork, cudaEventDisableTiming);
        cudaEventCreateWithFlags(&evJoin, cudaEventDisableTiming);
    }

    // Fork: topk (depends only on x) runs on s2 in parallel with the
    // precompute chain on the main stream.
    cudaEventRecord(evFork, 0);
    cudaStreamWaitEvent(s2, evFork, 0);
    topk_kernel<<<B, TK_T, 0, s2>>>(x, out, write_mask);
    cudaEventRecord(evJoin, s2);

    // Main-stream precompute chain.
    zero_G_kernel<<<5, 1024>>>();
    gvec_kernel<<<dim3(H/128, GV_HB), 128>>>(w1, b1, w2, b2);
    poly_stats_kernel<<<1, H>>>();
    emb_stats_kernel<<<313, 256>>>(emb);

    // Join, then stats + fuse.
    cudaStreamWaitEvent(0, evJoin, 0);
    token_stats_kernel<<<TOK/256, 256>>>();
    fuse_kernel<<<TOK/FU_TPB, 192>>>(emb, lnw, lnb, out);
}

// round 15
// speedup vs baseline: 2.3205x; 1.1603x over previous
#include <cuda_runtime.h>
#include <math.h>

#define B   256
#define NF  10000
#define H   768
#define K   512
#define NT  6
#define QN  (2*NT-1)
#define NPAIR (NT*(NT+1)/2)
#define TOK (B*K)

typedef unsigned long long u64;
__device__ __forceinline__ u64 pk2(float lo, float hi) {
    u64 r; asm("mov.b64 %0, {%1, %2};" : "=l"(r) : "f"(lo), "f"(hi)); return r;
}
__device__ __forceinline__ void upk2(u64 v, float& lo, float& hi) {
    asm("mov.b64 {%0, %1}, %2;" : "=f"(lo), "=f"(hi) : "l"(v));
}
__device__ __forceinline__ u64 fma2(u64 a, u64 b, u64 c) {
    u64 d; asm("fma.rn.f32x2 %0, %1, %2, %3;" : "=l"(d) : "l"(a), "l"(b), "l"(c)); return d;
}
__device__ __forceinline__ u64 add2(u64 a, u64 b) {
    u64 d; asm("add.rn.f32x2 %0, %1, %2;" : "=l"(d) : "l"(a), "l"(b)); return d;
}

// ---------------- scratch ----------------
__device__ __align__(16) float g_G[NT*H];
__device__ float g_SG[NT];
__device__ float g_Q[QN];
__device__ float g_Se[NF+1];
__device__ float g_Se2[NF+1];
__device__ __align__(16) float g_D[(NF+1)*8];   // 6 used + 2 pad for float4 alignment
__device__ float g_vals[TOK];
__device__ int   g_fid[TOK];
__device__ int   g_empty[B];

// ---------------- kernel 0: zero g_G / g_SG / g_Q for atomics --------------------
__global__ void zero_G_kernel() {
    int i = blockIdx.x * 1024 + threadIdx.x;
    if (i < NT*H) g_G[i] = 0.0f;
    if (i < NT)   g_SG[i] = 0.0f;
    if (i < QN)   g_Q[i]  = 0.0f;
}

// ---------------- kernel 1: G_k = w2^T c_k (+ b2 into k=0) ----------------------
#define GV_HB 32
#define GV_HC (H / GV_HB)
__global__ void gvec_kernel(const float* __restrict__ w1, const float* __restrict__ b1,
                            const float* __restrict__ w2, const float* __restrict__ b2) {
    __shared__ float sc[NT * GV_HC];
    int tid = threadIdx.x;                  // 128
    int d   = blockIdx.x * 128 + tid;
    int h0  = blockIdx.y * GV_HC;

    if (tid < GV_HC) {
        int h = h0 + tid;
        float a    = w1[h];
        float beta = b1[h];
        float phi = 0.3989422804f * expf(-0.5f * beta * beta);
        float Phi = 0.5f * (1.0f + erff(beta * 0.7071067812f));
        sc[0*GV_HC + tid] = beta * Phi;                 // gelu(beta)
        sc[1*GV_HC + tid] = (Phi + beta * phi) * a;     // gelu'(beta)*a
        float He_km2 = 1.0f, He_km1 = beta, fact = 1.0f, apow = a;
#pragma unroll
        for (int k = 2; k < NT; k++) {
            fact *= (float)k;
            apow *= a;
            float s  = (k & 1) ? -1.0f : 1.0f;
            float gk = phi * s * ((float)k * He_km2 - beta * He_km1);
            sc[k*GV_HC + tid] = gk * apow / fact;
            float He_k = beta * He_km1 - (float)(k - 1) * He_km2;
            He_km2 = He_km1; He_km1 = He_k;
        }
    }
    __syncthreads();

    float acc[NT];
#pragma unroll
    for (int k = 0; k < NT; k++) acc[k] = 0.0f;
#pragma unroll 4
    for (int h = 0; h < GV_HC; h++) {
        float w = w2[(size_t)(h0 + h) * H + d];
#pragma unroll
        for (int k = 0; k < NT; k++) acc[k] = fmaf(sc[k*GV_HC + h], w, acc[k]);
    }
    if (blockIdx.y == 0) acc[0] += b2[d];
#pragma unroll
    for (int k = 0; k < NT; k++) atomicAdd(&g_G[k*H + d], acc[k]);
}

// ---------------- kernel 1c: SG_k and Q_m — 27 parallel blocks -------------------
// Block s < NT:       SG_s = sum_d G_s[d]
// Block s >= NT:      pair (k,l), k<=l: Q[k+l] += (k==l?1:2) * sum_d G_k[d]*G_l[d]
__global__ void __launch_bounds__(128) poly_stats_kernel() {
    __shared__ float wred[4];
    int s    = blockIdx.x;
    int tid  = threadIdx.x;                 // 128
    int lane = tid & 31, warp = tid >> 5;

    int k, l;
    if (s < NT) { k = s; l = -1; }
    else {
        int p = s - NT; k = 0;
        while (p >= NT - k) { p -= NT - k; k++; }
        l = k + p;
    }

    float sum = 0.0f;
#pragma unroll
    for (int j = 0; j < H/128; j++) {
        int d = tid + j*128;
        float gk = g_G[k*H + d];
        sum += (l < 0) ? gk : gk * g_G[l*H + d];
    }
    sum += __shfl_down_sync(0xffffffffu, sum, 16);
    sum += __shfl_down_sync(0xffffffffu, sum, 8);
    sum += __shfl_down_sync(0xffffffffu, sum, 4);
    sum += __shfl_down_sync(0xffffffffu, sum, 2);
    sum += __shfl_down_sync(0xffffffffu, sum, 1);
    if (lane == 0) wred[warp] = sum;
    __syncthreads();
    if (tid == 0) {
        float t = wred[0] + wred[1] + wred[2] + wred[3];
        if (l < 0) atomicAdd(&g_SG[k], t);
        else       atomicAdd(&g_Q[k+l], (k == l ? 1.0f : 2.0f) * t);
    }
}

// ---------------- kernel 1d: per-emb-row Se, Se2, D_k (warp x 4 rows) ------------
__global__ void __launch_bounds__(256, 3) emb_stats_kernel(const float* __restrict__ emb) {
    __shared__ float4 sG[NT * 192];         // 18 KB
    int tid  = threadIdx.x;
    int lane = tid & 31, warp = tid >> 5;   // 8 warps
    const float4* G4 = (const float4*)g_G;
    for (int i = tid; i < NT * 192; i += 256) sG[i] = G4[i];
    __syncthreads();

    int r0 = (blockIdx.x * 8 + warp) * 4;
    if (r0 > NF) return;
    int nrow = NF + 1 - r0; if (nrow > 4) nrow = 4;

    const float4* emb4 = (const float4*)emb;
    float acc[4][NT+2];
#pragma unroll
    for (int t = 0; t < 4; t++)
#pragma unroll
        for (int i = 0; i < NT+2; i++) acc[t][i] = 0.0f;

#pragma unroll
    for (int j = 0; j < 6; j++) {
        int dg = lane + 32*j;
        float4 e[4];
#pragma unroll
        for (int t = 0; t < 4; t++)
            e[t] = (t < nrow) ? __ldg(&emb4[(size_t)(r0 + t) * 192 + dg])
                              : make_float4(0.f, 0.f, 0.f, 0.f);
#pragma unroll
        for (int t = 0; t < 4; t++) {
            acc[t][0] += e[t].x + e[t].y + e[t].z + e[t].w;
            acc[t][1] += e[t].x*e[t].x + e[t].y*e[t].y + e[t].z*e[t].z + e[t].w*e[t].w;
        }
#pragma unroll
        for (int k = 0; k < NT; k++) {
            float4 g = sG[k*192 + dg];
#pragma unroll
            for (int t = 0; t < 4; t++)
                acc[t][2+k] += e[t].x*g.x + e[t].y*g.y + e[t].z*g.z + e[t].w*g.w;
        }
    }
#pragma unroll
    for (int t = 0; t < 4; t++)
#pragma unroll
        for (int i = 0; i < NT+2; i++) {
            float v = acc[t][i];
            v += __shfl_down_sync(0xffffffffu, v, 16);
            v += __shfl_down_sync(0xffffffffu, v, 8);
            v += __shfl_down_sync(0xffffffffu, v, 4);
            v += __shfl_down_sync(0xffffffffu, v, 2);
            v += __shfl_down_sync(0xffffffffu, v, 1);
            acc[t][i] = v;
        }
    if (lane == 0) {
        for (int t = 0; t < nrow; t++) {
            int r = r0 + t;
            g_Se[r]  = acc[t][0];
            g_Se2[r] = acc[t][1];
            float4* D4 = (float4*)&g_D[r * 8];
            D4[0] = make_float4(acc[t][2], acc[t][3], acc[t][4], acc[t][5]);
            D4[1] = make_float4(acc[t][6], acc[t][7], 0.0f, 0.0f);
        }
    }
}

// ---------------- kernel 2: per-row top-512 (dependency-free: only reads x) ------
#define TK_T 512
#define TK_R 20      // 512*20 = 10240 >= NF
__global__ void __launch_bounds__(TK_T, 2) topk_kernel(const float* __restrict__ x,
                                                       float* __restrict__ out,
                                                       int write_mask) {
    __shared__ float xrow[NF];
    __shared__ unsigned long long cand[K];
    __shared__ int wsum[16];
    __shared__ int s_ge;
    __shared__ int scnt;

    int b    = blockIdx.x;
    int tid  = threadIdx.x;
    int lane = tid & 31, warp = tid >> 5;
    const float4* xr4 = (const float4*)(x + (size_t)b * NF);
    for (int i = tid; i < NF/4; i += TK_T) ((float4*)xrow)[i] = xr4[i];
    if (tid == 0) scnt = 0;
    __syncthreads();

    unsigned long long keys[TK_R];
#pragma unroll
    for (int r = 0; r < TK_R; r++) {
        int i = tid + r * TK_T;
        unsigned long long kb = 0ull;
        if (i < NF) {
            unsigned int ab = __float_as_uint(fabsf(xrow[i]));
            kb = ((unsigned long long)ab << 32) | (unsigned int)(~i);
        }
        keys[r] = kb;
    }

#define COUNT_GE(trial, res) { \
    int _c = 0; \
    _Pragma("unroll") \
    for (int _r = 0; _r < TK_R; _r++) _c += (keys[_r] >= (trial)) ? 1 : 0; \
    _c = __reduce_add_sync(0xffffffffu, _c); \
    if (lane == 0) wsum[warp] = _c; \
    __syncthreads(); \
    if (warp == 0) { \
        int _t = (lane < 16) ? wsum[lane] : 0; \
        _t = __reduce_add_sync(0xffffffffu, _t); \
        if (lane == 0) s_ge = _t; \
    } \
    __syncthreads(); \
    res = s_ge; }

    unsigned long long prefix = 0ull;
    int cbest = TK_T * TK_R;
    for (int bit = 62; bit >= 32; bit--) {
        unsigned long long trial = prefix | (1ull << bit);
        int c; COUNT_GE(trial, c);
        if (c >= K) { prefix = trial; cbest = c; }
    }
    if (cbest != K) {
        prefix |= 0xFFFFC000ull;            // constant bits 31..14 of every real key
        for (int bit = 13; bit >= 0; bit--) {
            unsigned long long trial = prefix | (1ull << bit);
            int c; COUNT_GE(trial, c);
            if (c >= K) prefix = trial;
        }
    }

#pragma unroll
    for (int r = 0; r < TK_R; r++) {
        if (keys[r] >= prefix) {
            int p = atomicAdd(&scnt, 1);
            if (p < K) cand[p] = keys[r];
        }
    }
    __syncthreads();

    // bitonic sort 512, descending
    for (int sz = 2; sz <= K; sz <<= 1) {
        for (int j = sz >> 1; j > 0; j >>= 1) {
            int ixj = tid ^ j;
            if (ixj > tid) {
                unsigned long long av = cand[tid], bv = cand[ixj];
                bool desc = ((tid & sz) == 0);
                if (desc ? (av < bv) : (av > bv)) { cand[tid] = bv; cand[ixj] = av; }
            }
            __syncthreads();
        }
    }

    unsigned long long key = cand[tid];
    unsigned int hi  = (unsigned int)(key >> 32);
    unsigned int idx = ~(unsigned int)key;
    int   active = (hi != 0u) ? 1 : 0;
    float v   = active ? xrow[idx] : 0.0f;
    int   fid = active ? (int)idx + 1 : 0;

    int nact  = __syncthreads_count(active);
    int empty = (nact == 0) ? 1 : 0;

    g_vals[b*K + tid] = v;
    g_fid [b*K + tid] = fid;
    if (tid == 0) g_empty[b] = empty;
    if (write_mask) {
        float m = (float)active;
        if (tid == 0 && empty) m = 1.0f;
        out[(size_t)TOK * H + (size_t)b * K + tid] = m;
    }
}

// ---------------- kernel 3: fused token-stats + gather + poly + LN ---------------
#define FU_TPB 64
__global__ void __launch_bounds__(192, 5) fuse_kernel(const float* __restrict__ emb,
                                                      const float* __restrict__ lnw,
                                                      const float* __restrict__ lnb,
                                                      float* __restrict__ out) {
    __shared__ float4 stok[FU_TPB];
    int dg = threadIdx.x;                   // 0..191 -> dims 4*dg..4*dg+3
    int t0 = blockIdx.x * FU_TPB;

    // ---- prologue: closed-form LN stats for this block's 64 tokens ----
    if (dg < FU_TPB) {
        int tok = t0 + dg;
        float v   = g_vals[tok];
        int   fid = g_fid[tok];

        float ps = g_SG[NT-1];
#pragma unroll
        for (int k = NT-2; k >= 0; k--) ps = fmaf(ps, v, g_SG[k]);
        float sumh = g_Se[fid] + ps;

        const float4* D4 = (const float4*)&g_D[fid * 8];
        float4 d0 = D4[0], d1 = D4[1];
        float D[NT] = {d0.x, d0.y, d0.z, d0.w, d1.x, d1.y};
        float pd = D[NT-1];
#pragma unroll
        for (int k = NT-2; k >= 0; k--) pd = fmaf(pd, v, D[k]);
        float pq = g_Q[QN-1];
#pragma unroll
        for (int m = QN-2; m >= 0; m--) pq = fmaf(pq, v, g_Q[m]);
        float sumh2 = g_Se2[fid] + 2.0f*pd + pq;

        float mu   = sumh * (1.0f / H);
        float var  = sumh2 * (1.0f / H) - mu * mu;
        float rstd = rsqrtf(var + 1e-5f);

        unsigned int enc = (unsigned int)fid;
        if ((tok & (K-1)) == 0 && g_empty[tok >> 9]) enc |= 0x80000000u;
        stok[dg] = make_float4(v, __uint_as_float(enc), mu, rstd);
    }

    u64 Gxy[NT], Gzw[NT];
#pragma unroll
    for (int k = 0; k < NT; k++) {
        float4 g = ((const float4*)g_G)[k*192 + dg];
        Gxy[k] = pk2(g.x, g.y);
        Gzw[k] = pk2(g.z, g.w);
    }
    float4 lwf = ((const float4*)lnw)[dg];
    float4 lbf = ((const float4*)lnb)[dg];
    u64 lwxy = pk2(lwf.x, lwf.y), lwzw = pk2(lwf.z, lwf.w);
    u64 lbxy = pk2(lbf.x, lbf.y), lbzw = pk2(lbf.z, lbf.w);
    const float4* emb4 = (const float4*)emb;
    float4* out4 = (float4*)out;
    __syncthreads();

    for (int tt = 0; tt < FU_TPB; tt += 8) {
#pragma unroll
        for (int j = 0; j < 8; j++) {
            int tok = t0 + tt + j;
            float4 t = stok[tt + j];
            int enc = __float_as_int(t.y);
            float4 e = __ldg(&emb4[(size_t)(enc & 0x7fffffff) * 192 + dg]);
            float v = t.x, mu = t.z, rstd = t.w;

            u64 vv = pk2(v, v);
            u64 rr = pk2(rstd, rstd);
            float nmr = -mu * rstd;
            u64 mm = pk2(nmr, nmr);

            u64 pxy = Gxy[NT-1], pzw = Gzw[NT-1];
#pragma unroll
            for (int k = NT-2; k >= 0; k--) {
                pxy = fma2(pxy, vv, Gxy[k]);
                pzw = fma2(pzw, vv, Gzw[k]);
            }
            u64 hxy = add2(pk2(e.x, e.y), pxy);
            u64 hzw = add2(pk2(e.z, e.w), pzw);
            u64 txy = fma2(hxy, rr, mm);
            u64 tzw = fma2(hzw, rr, mm);
            u64 oxy = fma2(txy, lwxy, lbxy);
            u64 ozw = fma2(tzw, lwzw, lbzw);

            float4 o;
            upk2(oxy, o.x, o.y);
            upk2(ozw, o.z, o.w);
            if (enc < 0) { o.x = 0.0f; o.y = 0.0f; o.z = 0.0f; o.w = 0.0f; }
            __stcs(&out4[(size_t)tok * 192 + dg], o);
        }
    }
}

// ---------------- launch --------------------------------------------------------
extern "C" void kernel_launch(void* const* d_in, const int* in_sizes, int n_in,
                              void* d_out, int out_size) {
    const float* x   = (const float*)d_in[0];
    const float* emb = (const float*)d_in[1];
    const float* w1  = (const float*)d_in[2];
    const float* b1  = (const float*)d_in[3];
    const float* w2  = (const float*)d_in[4];
    const float* b2  = (const float*)d_in[5];
    const float* lnw = (const float*)d_in[6];
    const float* lnb = (const float*)d_in[7];
    float* out = (float*)d_out;

    int write_mask = (out_size >= TOK * H + TOK) ? 1 : 0;

    static cudaStream_t s2 = nullptr;
    static cudaEvent_t evFork = nullptr, evJoin = nullptr;
    if (s2 == nullptr) {
        cudaStreamCreateWithFlags(&s2, cudaStreamNonBlocking);
        cudaEventCreateWithFlags(&evFork, cudaEventDisableTiming);
        cudaEventCreateWithFlags(&evJoin, cudaEventDisableTiming);
    }

    // Fork: topk (depends only on x) runs on s2 in parallel with the
    // precompute chain on the main stream.
    cudaEventRecord(evFork, 0);
    cudaStreamWaitEvent(s2, evFork, 0);
    topk_kernel<<<B, TK_T, 0, s2>>>(x, out, write_mask);
    cudaEventRecord(evJoin, s2);

    // Main-stream precompute chain.
    zero_G_kernel<<<5, 1024>>>();
    gvec_kernel<<<dim3(H/128, GV_HB), 128>>>(w1, b1, w2, b2);
    poly_stats_kernel<<<NT + NPAIR, 128>>>();
    emb_stats_kernel<<<313, 256>>>(emb);

    // Join, then fused stats+gather+LN.
    cudaStreamWaitEvent(0, evJoin, 0);
    fuse_kernel<<<TOK/FU_TPB, 192>>>(emb, lnw, lnb, out);
}